// round 7
// baseline (speedup 1.0000x reference)
#include <cuda_runtime.h>
#include <stdint.h>

#define N_NODES 50000
#define N_EDGES 50000
#define N_PAIRS 800000
#define IN_CH   512
#define HID0    256
#define HID1    128
#define N_TGT   32

// ---------------- scratch (static device globals; no cudaMalloc allowed) ----
__device__ float g_h   [(size_t)N_NODES * HID0];   // GEMM output
__device__ float g_fte [(size_t)N_EDGES * HID0];   // edge features
__device__ float g_hout[(size_t)N_NODES * HID0];   // hyconv output / next input
__device__ float g_invDe[N_EDGES], g_invDn[N_NODES];
__device__ int   g_cnt_e[N_EDGES], g_cnt_n[N_NODES];
__device__ int   g_off_e[N_EDGES], g_off_n[N_NODES];
__device__ int   g_cur_e[N_EDGES], g_cur_n[N_NODES];
__device__ int   g_adj_e[N_PAIRS];   // node ids grouped by edge
__device__ int   g_adj_n[N_PAIRS];   // edge ids grouped by node
__device__ int   g_bsum[2][64];      // per-block scan partials
__device__ unsigned char g_mask[(size_t)N_NODES * (HID0 + HID1)]; // layer0 | layer1
__device__ float g_pool[HID1];

// ---------------- threefry2x32 (exact JAX semantics) ------------------------
__host__ __device__ __forceinline__ uint32_t rotl32(uint32_t x, int d) {
    return (x << d) | (x >> (32 - d));
}
__host__ __device__ __forceinline__ void threefry2x32(
    uint32_t k0, uint32_t k1, uint32_t x0, uint32_t x1,
    uint32_t& o0, uint32_t& o1)
{
    uint32_t k2 = k0 ^ k1 ^ 0x1BD11BDAu;
    x0 += k0; x1 += k1;
    x0 += x1; x1 = rotl32(x1,13); x1 ^= x0;
    x0 += x1; x1 = rotl32(x1,15); x1 ^= x0;
    x0 += x1; x1 = rotl32(x1,26); x1 ^= x0;
    x0 += x1; x1 = rotl32(x1, 6); x1 ^= x0;
    x0 += k1; x1 += k2 + 1u;
    x0 += x1; x1 = rotl32(x1,17); x1 ^= x0;
    x0 += x1; x1 = rotl32(x1,29); x1 ^= x0;
    x0 += x1; x1 = rotl32(x1,16); x1 ^= x0;
    x0 += x1; x1 = rotl32(x1,24); x1 ^= x0;
    x0 += k2; x1 += k0 + 2u;
    x0 += x1; x1 = rotl32(x1,13); x1 ^= x0;
    x0 += x1; x1 = rotl32(x1,15); x1 ^= x0;
    x0 += x1; x1 = rotl32(x1,26); x1 ^= x0;
    x0 += x1; x1 = rotl32(x1, 6); x1 ^= x0;
    x0 += k0; x1 += k1 + 3u;
    x0 += x1; x1 = rotl32(x1,17); x1 ^= x0;
    x0 += x1; x1 = rotl32(x1,29); x1 ^= x0;
    x0 += x1; x1 = rotl32(x1,16); x1 ^= x0;
    x0 += x1; x1 = rotl32(x1,24); x1 ^= x0;
    x0 += k1; x1 += k2 + 4u;
    x0 += x1; x1 = rotl32(x1,13); x1 ^= x0;
    x0 += x1; x1 = rotl32(x1,15); x1 ^= x0;
    x0 += x1; x1 = rotl32(x1,26); x1 ^= x0;
    x0 += x1; x1 = rotl32(x1, 6); x1 ^= x0;
    x0 += k2; x1 += k0 + 5u;
    o0 = x0; o1 = x1;
}

// ---------------- small setup kernels ---------------------------------------
__global__ void k_zero() {
    int i = blockIdx.x * blockDim.x + threadIdx.x;
    if (i < N_EDGES) g_cnt_e[i] = 0;
    if (i < N_NODES) g_cnt_n[i] = 0;
    if (i < HID1)    g_pool[i]  = 0.f;
}

__global__ void k_degree(const int* __restrict__ H) {
    int p = blockIdx.x * blockDim.x + threadIdx.x;
    if (p < N_PAIRS) {
        atomicAdd(&g_cnt_n[H[p]], 1);
        atomicAdd(&g_cnt_e[H[N_PAIRS + p]], 1);
    }
}

// ---------------- 3-phase parallel exclusive scan ----------------------------
__global__ void k_scan_part() {
    int arr = blockIdx.y;
    const int* cnt = arr ? g_cnt_n : g_cnt_e;
    int* off       = arr ? g_off_n : g_off_e;
    __shared__ int wsum[32];
    int i = blockIdx.x * 1024 + threadIdx.x;
    int lane = threadIdx.x & 31, w = threadIdx.x >> 5;
    int v = (i < N_EDGES) ? cnt[i] : 0;
    int x = v;
    #pragma unroll
    for (int o = 1; o < 32; o <<= 1) {
        int y = __shfl_up_sync(0xffffffffu, x, o);
        if (lane >= o) x += y;
    }
    if (lane == 31) wsum[w] = x;
    __syncthreads();
    if (w == 0) {
        int s = wsum[lane];
        #pragma unroll
        for (int o = 1; o < 32; o <<= 1) {
            int y = __shfl_up_sync(0xffffffffu, s, o);
            if (lane >= o) s += y;
        }
        wsum[lane] = s;
    }
    __syncthreads();
    int incl = x + ((w > 0) ? wsum[w - 1] : 0);
    if (i < N_EDGES) off[i] = incl - v;          // local exclusive
    if (threadIdx.x == 1023) g_bsum[arr][blockIdx.x] = incl;
}

__global__ void k_scan_top() {
    int arr = blockIdx.x;
    __shared__ int s[64];
    int t = threadIdx.x;
    s[t] = (t < 49) ? g_bsum[arr][t] : 0;
    __syncthreads();
    #pragma unroll
    for (int o = 1; o < 64; o <<= 1) {
        int val = (t >= o) ? s[t - o] : 0;
        __syncthreads();
        s[t] += val;
        __syncthreads();
    }
    if (t < 49) g_bsum[arr][t] = s[t];
}

__global__ void k_scan_add() {
    int arr = blockIdx.y;
    int i = blockIdx.x * 1024 + threadIdx.x;
    if (i >= N_EDGES) return;
    int add = blockIdx.x ? g_bsum[arr][blockIdx.x - 1] : 0;
    if (arr == 0) {
        int o = g_off_e[i] + add;
        g_off_e[i] = o; g_cur_e[i] = o;
        g_invDe[i] = 1.0f / fmaxf((float)g_cnt_e[i], 1.0f);
    } else {
        int o = g_off_n[i] + add;
        g_off_n[i] = o; g_cur_n[i] = o;
        g_invDn[i] = 1.0f / fmaxf((float)g_cnt_n[i], 1.0f);
    }
}

__global__ void k_fill(const int* __restrict__ H) {
    int p = blockIdx.x * blockDim.x + threadIdx.x;
    if (p < N_PAIRS) {
        int n = H[p], e = H[N_PAIRS + p];
        g_adj_e[atomicAdd(&g_cur_e[e], 1)] = n;
        g_adj_n[atomicAdd(&g_cur_n[n], 1)] = e;
    }
}

// ---------------- dropout mask (JAX partitionable threefry) ------------------
// word(i) = o0 ^ o1 of threefry(key, 0, i); keep <=> top bit 0.
__global__ void k_mask(uint32_t k0, uint32_t k1, int n, int base) {
    int i = blockIdx.x * blockDim.x + threadIdx.x;
    if (i < n) {
        uint32_t o0, o1;
        threefry2x32(k0, k1, 0u, (uint32_t)i, o0, o1);
        g_mask[base + i] = ((o0 ^ o1) >> 31) == 0u;
    }
}

// ---------------- SGEMM: FFMA2, single-buffer (round-5 config) ---------------
#define FMA2(d, a, b) asm("fma.rn.f32x2 %0, %1, %2, %0;" : "+l"(d) : "l"(a), "l"(b))

__global__ void k_gemm(const float* __restrict__ A, const float* __restrict__ B,
                       float* __restrict__ C, int M, int N, int K) {
    __shared__ float As[8][128];
    __shared__ float Bs[8][132];
    int tid = threadIdx.x;
    int bm = blockIdx.x * 128;
    int bn = blockIdx.y * 128;
    int tx = tid & 15, ty = tid >> 4;
    int arow = tid >> 1, acol = (tid & 1) << 2;
    int brow = tid >> 5, bcol = (tid & 31) << 2;
    unsigned long long acc[8][4];
    #pragma unroll
    for (int i = 0; i < 8; i++)
        #pragma unroll
        for (int j = 0; j < 4; j++) acc[i][j] = 0ull;

    for (int k0 = 0; k0 < K; k0 += 8) {
        float4 av;
        if (bm + arow < M) av = *(const float4*)(A + (size_t)(bm + arow) * K + k0 + acol);
        else av = make_float4(0.f, 0.f, 0.f, 0.f);
        As[acol + 0][arow] = av.x; As[acol + 1][arow] = av.y;
        As[acol + 2][arow] = av.z; As[acol + 3][arow] = av.w;
        float4 bv = *(const float4*)(B + (size_t)(k0 + brow) * N + bn + bcol);
        Bs[brow][bcol + 0] = bv.x; Bs[brow][bcol + 1] = bv.y;
        Bs[brow][bcol + 2] = bv.z; Bs[brow][bcol + 3] = bv.w;
        __syncthreads();
        #pragma unroll
        for (int kk = 0; kk < 8; kk++) {
            float4 a03 = *(const float4*)&As[kk][ty * 8];
            float4 a47 = *(const float4*)&As[kk][ty * 8 + 4];
            ulonglong2 b01 = *(const ulonglong2*)&Bs[kk][tx * 8];
            ulonglong2 b23 = *(const ulonglong2*)&Bs[kk][tx * 8 + 4];
            float avr[8] = {a03.x, a03.y, a03.z, a03.w, a47.x, a47.y, a47.z, a47.w};
            #pragma unroll
            for (int i = 0; i < 8; i++) {
                unsigned long long a2;
                asm("mov.b64 %0, {%1, %1};" : "=l"(a2) : "f"(avr[i]));
                FMA2(acc[i][0], a2, b01.x);
                FMA2(acc[i][1], a2, b01.y);
                FMA2(acc[i][2], a2, b23.x);
                FMA2(acc[i][3], a2, b23.y);
            }
        }
        __syncthreads();
    }
    #pragma unroll
    for (int i = 0; i < 8; i++) {
        int row = bm + ty * 8 + i;
        if (row < M) {
            float2 p0 = *(float2*)&acc[i][0];
            float2 p1 = *(float2*)&acc[i][1];
            float2 p2 = *(float2*)&acc[i][2];
            float2 p3 = *(float2*)&acc[i][3];
            float4* cp = (float4*)(C + (size_t)row * N + bn + tx * 8);
            cp[0] = make_float4(p0.x, p0.y, p1.x, p1.y);
            cp[1] = make_float4(p2.x, p2.y, p3.x, p3.y);
        }
    }
}

// ---------------- sparse gathers (CSR, no atomics) ---------------------------
template<int C>
__global__ void k_edge_gather(const float* __restrict__ h, float* __restrict__ fte) {
    int e = blockIdx.x;
    int c = threadIdx.x;
    int s = g_off_e[e], m = g_cnt_e[e];
    const int* adj = g_adj_e + s;
    float acc = 0.f;
    int j = 0;
    for (; j + 4 <= m; j += 4) {
        int n0 = adj[j], n1 = adj[j + 1], n2 = adj[j + 2], n3 = adj[j + 3];
        float a = h[(size_t)n0 * C + c];
        float b = h[(size_t)n1 * C + c];
        float d = h[(size_t)n2 * C + c];
        float f = h[(size_t)n3 * C + c];
        acc += a + b + d + f;
    }
    for (; j < m; j++) acc += h[(size_t)adj[j] * C + c];
    fte[(size_t)e * C + c] = acc * g_invDe[e];
}

// node aggregation + bias + leaky relu + precomputed dropout mask
template<int C>
__global__ void k_node_apply(const float* __restrict__ fte,
                             const float* __restrict__ bias,
                             float* __restrict__ out, int mbase) {
    int n = blockIdx.x;
    int c = threadIdx.x;
    int s = g_off_n[n], m = g_cnt_n[n];
    const int* adj = g_adj_n + s;
    float acc = 0.f;
    int j = 0;
    for (; j + 4 <= m; j += 4) {
        int e0 = adj[j], e1 = adj[j + 1], e2 = adj[j + 2], e3 = adj[j + 3];
        float a = fte[(size_t)e0 * C + c];
        float b = fte[(size_t)e1 * C + c];
        float d = fte[(size_t)e2 * C + c];
        float f = fte[(size_t)e3 * C + c];
        acc += a + b + d + f;
    }
    for (; j < m; j++) acc += fte[(size_t)adj[j] * C + c];
    float v = acc * g_invDn[n] + bias[c];
    v = (v >= 0.f) ? v : 0.01f * v;          // leaky relu
    int idx = n * C + c;
    v = g_mask[mbase + idx] ? v * 2.0f : 0.0f;
    out[(size_t)idx] = v;
}

// ---------------- dropmax (top-12 zeroed, JAX tie-break) + pooled sum -------
__global__ void k_dropmax(const float* __restrict__ h, float* __restrict__ feats,
                          float* __restrict__ pool) {
    __shared__ float s_pool[HID1];
    int t = threadIdx.x;
    if (t < HID1) s_pool[t] = 0.f;
    __syncthreads();
    int warp = t >> 5, lane = t & 31;
    int row = blockIdx.x * (blockDim.x >> 5) + warp;
    if (row < N_NODES) {
        float4 v4 = ((const float4*)(h + (size_t)row * HID1))[lane];
        float v[4] = {v4.x, v4.y, v4.z, v4.w};
        unsigned long long key[4];
        bool rem[4] = {false, false, false, false};
        #pragma unroll
        for (int j = 0; j < 4; j++) {
            uint32_t b = __float_as_uint(v[j]);
            uint32_t ord = (b & 0x80000000u) ? ~b : (b | 0x80000000u);
            key[j] = ((unsigned long long)ord << 32) |
                     (unsigned long long)(uint32_t)(127 - (lane * 4 + j));
        }
        for (int it = 0; it < 12; it++) {
            unsigned long long best = 0ull;
            #pragma unroll
            for (int j = 0; j < 4; j++) if (!rem[j] && key[j] > best) best = key[j];
            #pragma unroll
            for (int o = 16; o > 0; o >>= 1) {
                unsigned long long other = __shfl_xor_sync(0xffffffffu, best, o);
                if (other > best) best = other;
            }
            #pragma unroll
            for (int j = 0; j < 4; j++) if (key[j] == best) rem[j] = true;
        }
        #pragma unroll
        for (int j = 0; j < 4; j++) if (rem[j]) v[j] = 0.f;
        ((float4*)(feats + (size_t)row * HID1))[lane] =
            make_float4(v[0], v[1], v[2], v[3]);
        #pragma unroll
        for (int j = 0; j < 4; j++) atomicAdd(&s_pool[lane * 4 + j], v[j]);
    }
    __syncthreads();
    if (t < HID1) atomicAdd(&pool[t], s_pool[t]);
}

// ---------------- head: mean, fc, sigmoid ------------------------------------
__global__ void k_final(const float* __restrict__ Wfc, const float* __restrict__ bfc,
                        float* __restrict__ d_out) {
    __shared__ float p[HID1];
    int t = threadIdx.x;
    if (t < HID1) {
        float pv = g_pool[t] * (1.0f / (float)N_NODES);
        p[t] = pv;
        d_out[32 + (size_t)N_NODES * HID1 + t] = pv;   // feats_pool
    }
    __syncthreads();
    if (t < N_TGT) {
        float acc = bfc[t];
        #pragma unroll 8
        for (int c = 0; c < HID1; c++) acc += p[c] * Wfc[c * N_TGT + t];
        d_out[t] = 1.0f / (1.0f + expf(-acc));
    }
}

// ---------------- launch ------------------------------------------------------
extern "C" void kernel_launch(void* const* d_in, const int* in_sizes, int n_in,
                              void* d_out, int out_size) {
    const float* x   = (const float*)d_in[0];
    const int*   H   = (const int*)  d_in[1];
    const float* W0  = (const float*)d_in[2];
    const float* b0  = (const float*)d_in[3];
    const float* W1  = (const float*)d_in[4];
    const float* b1  = (const float*)d_in[5];
    const float* Wfc = (const float*)d_in[6];
    const float* bfc = (const float*)d_in[7];
    float* out = (float*)d_out;

    float *p_h, *p_fte, *p_hout, *p_pool;
    cudaGetSymbolAddress((void**)&p_h,    g_h);
    cudaGetSymbolAddress((void**)&p_fte,  g_fte);
    cudaGetSymbolAddress((void**)&p_hout, g_hout);
    cudaGetSymbolAddress((void**)&p_pool, g_pool);

    // side stream + fork/join events (created once, outside capture; reused)
    static cudaStream_t s_b = 0;
    static cudaEvent_t  e_fork = 0, e_join = 0;
    if (!s_b) {
        cudaStreamCreateWithFlags(&s_b, cudaStreamNonBlocking);
        cudaEventCreateWithFlags(&e_fork, cudaEventDisableTiming);
        cudaEventCreateWithFlags(&e_join, cudaEventDisableTiming);
    }

    // JAX keys: base key(42) = (0,42); fold_in(key, i) = threefry(key, (0, i))
    uint32_t l0k0, l0k1, l1k0, l1k1;
    threefry2x32(0u, 42u, 0u, 0u, l0k0, l0k1);
    threefry2x32(0u, 42u, 0u, 1u, l1k0, l1k1);

    const int NBLK = (N_EDGES + 1023) / 1024;   // 49

    // ---- fork: CSR build + masks on s_b, GEMM0 on main ----------------------
    // Enqueue order puts k_gemm at kernel-launch index 5 so ncu (-s 5 -c 1)
    // profiles the dominant GEMM instead of a scan kernel.
    cudaEventRecord(e_fork, 0);
    cudaStreamWaitEvent(s_b, e_fork, 0);

    k_zero     <<<196, 256, 0, s_b>>>();                                   // 0
    k_degree   <<<(N_PAIRS + 255) / 256, 256, 0, s_b>>>(H);                // 1
    k_scan_part<<<dim3(NBLK, 2), 1024, 0, s_b>>>();                        // 2
    k_scan_top <<<2, 64, 0, s_b>>>();                                      // 3
    k_scan_add <<<dim3(NBLK, 2), 1024, 0, s_b>>>();                        // 4

    k_gemm<<<dim3((N_NODES + 127) / 128, HID0 / 128), 256>>>(x, W0, p_h,   // 5
                                                             N_NODES, HID0, IN_CH);

    k_fill     <<<(N_PAIRS + 255) / 256, 256, 0, s_b>>>(H);                // 6
    k_mask     <<<(N_NODES * HID0 + 1023) / 1024, 1024, 0, s_b>>>(         // 7
                   l0k0, l0k1, N_NODES * HID0, 0);
    k_mask     <<<(N_NODES * HID1 + 1023) / 1024, 1024, 0, s_b>>>(         // 8
                   l1k0, l1k1, N_NODES * HID1, N_NODES * HID0);

    cudaEventRecord(e_join, s_b);
    cudaStreamWaitEvent(0, e_join, 0);

    // ----- layer 0 (rest) -----
    k_edge_gather<HID0><<<N_EDGES, HID0>>>(p_h, p_fte);
    k_node_apply<HID0><<<N_NODES, HID0>>>(p_fte, b0, p_hout, 0);

    // ----- layer 1 -----
    k_gemm<<<dim3((N_NODES + 127) / 128, HID1 / 128), 256>>>(p_hout, W1, p_h,
                                                             N_NODES, HID1, HID0);
    k_edge_gather<HID1><<<N_EDGES, HID1>>>(p_h, p_fte);
    k_node_apply<HID1><<<N_NODES, HID1>>>(p_fte, b1, p_hout, N_NODES * HID0);

    // ----- dropmax + pool + head -----
    k_dropmax<<<(N_NODES + 7) / 8, 256>>>(p_hout, out + 32, p_pool);
    k_final<<<1, 128>>>(Wfc, bfc, out);
}

// round 8
// speedup vs baseline: 1.3499x; 1.3499x over previous
#include <cuda_runtime.h>
#include <stdint.h>

#define N_NODES 50000
#define N_EDGES 50000
#define N_PAIRS 800000
#define IN_CH   512
#define HID0    256
#define HID1    128
#define N_TGT   32

// ---------------- scratch (static device globals; no cudaMalloc allowed) ----
__device__ float g_h   [(size_t)N_NODES * HID0];   // GEMM output
__device__ float g_fte [(size_t)N_EDGES * HID0];   // edge features
__device__ float g_hout[(size_t)N_NODES * HID0];   // hyconv output / next input
__device__ float g_invDe[N_EDGES], g_invDn[N_NODES];
__device__ int   g_cnt_e[N_EDGES], g_cnt_n[N_NODES];
__device__ int   g_off_e[N_EDGES], g_off_n[N_NODES];
__device__ int   g_cur_e[N_EDGES], g_cur_n[N_NODES];
__device__ int   g_adj_e[N_PAIRS];   // node ids grouped by edge
__device__ int   g_adj_n[N_PAIRS];   // edge ids grouped by node
__device__ int   g_bsum[2][64];      // per-block scan partials
__device__ float g_pool[HID1];

// ---------------- threefry2x32 (exact JAX semantics) ------------------------
__host__ __device__ __forceinline__ uint32_t rotl32(uint32_t x, int d) {
    return (x << d) | (x >> (32 - d));
}
__host__ __device__ __forceinline__ void threefry2x32(
    uint32_t k0, uint32_t k1, uint32_t x0, uint32_t x1,
    uint32_t& o0, uint32_t& o1)
{
    uint32_t k2 = k0 ^ k1 ^ 0x1BD11BDAu;
    x0 += k0; x1 += k1;
    x0 += x1; x1 = rotl32(x1,13); x1 ^= x0;
    x0 += x1; x1 = rotl32(x1,15); x1 ^= x0;
    x0 += x1; x1 = rotl32(x1,26); x1 ^= x0;
    x0 += x1; x1 = rotl32(x1, 6); x1 ^= x0;
    x0 += k1; x1 += k2 + 1u;
    x0 += x1; x1 = rotl32(x1,17); x1 ^= x0;
    x0 += x1; x1 = rotl32(x1,29); x1 ^= x0;
    x0 += x1; x1 = rotl32(x1,16); x1 ^= x0;
    x0 += x1; x1 = rotl32(x1,24); x1 ^= x0;
    x0 += k2; x1 += k0 + 2u;
    x0 += x1; x1 = rotl32(x1,13); x1 ^= x0;
    x0 += x1; x1 = rotl32(x1,15); x1 ^= x0;
    x0 += x1; x1 = rotl32(x1,26); x1 ^= x0;
    x0 += x1; x1 = rotl32(x1, 6); x1 ^= x0;
    x0 += k0; x1 += k1 + 3u;
    x0 += x1; x1 = rotl32(x1,17); x1 ^= x0;
    x0 += x1; x1 = rotl32(x1,29); x1 ^= x0;
    x0 += x1; x1 = rotl32(x1,16); x1 ^= x0;
    x0 += x1; x1 = rotl32(x1,24); x1 ^= x0;
    x0 += k1; x1 += k2 + 4u;
    x0 += x1; x1 = rotl32(x1,13); x1 ^= x0;
    x0 += x1; x1 = rotl32(x1,15); x1 ^= x0;
    x0 += x1; x1 = rotl32(x1,26); x1 ^= x0;
    x0 += x1; x1 = rotl32(x1, 6); x1 ^= x0;
    x0 += k2; x1 += k0 + 5u;
    o0 = x0; o1 = x1;
}

// ---------------- small setup kernels ---------------------------------------
__global__ void k_zero() {
    int i = blockIdx.x * blockDim.x + threadIdx.x;
    if (i < N_EDGES) g_cnt_e[i] = 0;
    if (i < N_NODES) g_cnt_n[i] = 0;
    if (i < HID1)    g_pool[i]  = 0.f;
}

__global__ void k_degree(const int* __restrict__ H) {
    int p = blockIdx.x * blockDim.x + threadIdx.x;
    if (p < N_PAIRS) {
        atomicAdd(&g_cnt_n[H[p]], 1);
        atomicAdd(&g_cnt_e[H[N_PAIRS + p]], 1);
    }
}

// ---------------- 3-phase parallel exclusive scan ----------------------------
__global__ void k_scan_part() {
    int arr = blockIdx.y;
    const int* cnt = arr ? g_cnt_n : g_cnt_e;
    int* off       = arr ? g_off_n : g_off_e;
    __shared__ int wsum[32];
    int i = blockIdx.x * 1024 + threadIdx.x;
    int lane = threadIdx.x & 31, w = threadIdx.x >> 5;
    int v = (i < N_EDGES) ? cnt[i] : 0;
    int x = v;
    #pragma unroll
    for (int o = 1; o < 32; o <<= 1) {
        int y = __shfl_up_sync(0xffffffffu, x, o);
        if (lane >= o) x += y;
    }
    if (lane == 31) wsum[w] = x;
    __syncthreads();
    if (w == 0) {
        int s = wsum[lane];
        #pragma unroll
        for (int o = 1; o < 32; o <<= 1) {
            int y = __shfl_up_sync(0xffffffffu, s, o);
            if (lane >= o) s += y;
        }
        wsum[lane] = s;
    }
    __syncthreads();
    int incl = x + ((w > 0) ? wsum[w - 1] : 0);
    if (i < N_EDGES) off[i] = incl - v;          // local exclusive
    if (threadIdx.x == 1023) g_bsum[arr][blockIdx.x] = incl;
}

__global__ void k_scan_top() {
    int arr = blockIdx.x;
    __shared__ int s[64];
    int t = threadIdx.x;
    s[t] = (t < 49) ? g_bsum[arr][t] : 0;
    __syncthreads();
    #pragma unroll
    for (int o = 1; o < 64; o <<= 1) {
        int val = (t >= o) ? s[t - o] : 0;
        __syncthreads();
        s[t] += val;
        __syncthreads();
    }
    if (t < 49) g_bsum[arr][t] = s[t];
}

__global__ void k_scan_add() {
    int arr = blockIdx.y;
    int i = blockIdx.x * 1024 + threadIdx.x;
    if (i >= N_EDGES) return;
    int add = blockIdx.x ? g_bsum[arr][blockIdx.x - 1] : 0;
    if (arr == 0) {
        int o = g_off_e[i] + add;
        g_off_e[i] = o; g_cur_e[i] = o;
        g_invDe[i] = 1.0f / fmaxf((float)g_cnt_e[i], 1.0f);
    } else {
        int o = g_off_n[i] + add;
        g_off_n[i] = o; g_cur_n[i] = o;
        g_invDn[i] = 1.0f / fmaxf((float)g_cnt_n[i], 1.0f);
    }
}

__global__ void k_fill(const int* __restrict__ H) {
    int p = blockIdx.x * blockDim.x + threadIdx.x;
    if (p < N_PAIRS) {
        int n = H[p], e = H[N_PAIRS + p];
        g_adj_e[atomicAdd(&g_cur_e[e], 1)] = n;
        g_adj_n[atomicAdd(&g_cur_n[n], 1)] = e;
    }
}

// ---------------- SGEMM: FFMA2, single-buffer (round-5 config) ---------------
#define FMA2(d, a, b) asm("fma.rn.f32x2 %0, %1, %2, %0;" : "+l"(d) : "l"(a), "l"(b))

__global__ void k_gemm(const float* __restrict__ A, const float* __restrict__ B,
                       float* __restrict__ C, int M, int N, int K) {
    __shared__ float As[8][128];
    __shared__ float Bs[8][132];
    int tid = threadIdx.x;
    int bm = blockIdx.x * 128;
    int bn = blockIdx.y * 128;
    int tx = tid & 15, ty = tid >> 4;
    int arow = tid >> 1, acol = (tid & 1) << 2;
    int brow = tid >> 5, bcol = (tid & 31) << 2;
    unsigned long long acc[8][4];
    #pragma unroll
    for (int i = 0; i < 8; i++)
        #pragma unroll
        for (int j = 0; j < 4; j++) acc[i][j] = 0ull;

    for (int k0 = 0; k0 < K; k0 += 8) {
        float4 av;
        if (bm + arow < M) av = *(const float4*)(A + (size_t)(bm + arow) * K + k0 + acol);
        else av = make_float4(0.f, 0.f, 0.f, 0.f);
        As[acol + 0][arow] = av.x; As[acol + 1][arow] = av.y;
        As[acol + 2][arow] = av.z; As[acol + 3][arow] = av.w;
        float4 bv = *(const float4*)(B + (size_t)(k0 + brow) * N + bn + bcol);
        Bs[brow][bcol + 0] = bv.x; Bs[brow][bcol + 1] = bv.y;
        Bs[brow][bcol + 2] = bv.z; Bs[brow][bcol + 3] = bv.w;
        __syncthreads();
        #pragma unroll
        for (int kk = 0; kk < 8; kk++) {
            float4 a03 = *(const float4*)&As[kk][ty * 8];
            float4 a47 = *(const float4*)&As[kk][ty * 8 + 4];
            ulonglong2 b01 = *(const ulonglong2*)&Bs[kk][tx * 8];
            ulonglong2 b23 = *(const ulonglong2*)&Bs[kk][tx * 8 + 4];
            float avr[8] = {a03.x, a03.y, a03.z, a03.w, a47.x, a47.y, a47.z, a47.w};
            #pragma unroll
            for (int i = 0; i < 8; i++) {
                unsigned long long a2;
                asm("mov.b64 %0, {%1, %1};" : "=l"(a2) : "f"(avr[i]));
                FMA2(acc[i][0], a2, b01.x);
                FMA2(acc[i][1], a2, b01.y);
                FMA2(acc[i][2], a2, b23.x);
                FMA2(acc[i][3], a2, b23.y);
            }
        }
        __syncthreads();
    }
    #pragma unroll
    for (int i = 0; i < 8; i++) {
        int row = bm + ty * 8 + i;
        if (row < M) {
            float2 p0 = *(float2*)&acc[i][0];
            float2 p1 = *(float2*)&acc[i][1];
            float2 p2 = *(float2*)&acc[i][2];
            float2 p3 = *(float2*)&acc[i][3];
            float4* cp = (float4*)(C + (size_t)row * N + bn + tx * 8);
            cp[0] = make_float4(p0.x, p0.y, p1.x, p1.y);
            cp[1] = make_float4(p2.x, p2.y, p3.x, p3.y);
        }
    }
}

// ---------------- sparse gathers (CSR, float4-vectorized) --------------------
// one block per edge, C/4 threads, LDG.128 gathers
template<int C>
__global__ void k_edge_gather(const float* __restrict__ h, float* __restrict__ fte) {
    int e = blockIdx.x;
    int c4 = threadIdx.x;                       // float4 lane
    int s = g_off_e[e], m = g_cnt_e[e];
    const int* adj = g_adj_e + s;
    const float4* h4 = (const float4*)h;
    float4 acc = make_float4(0.f, 0.f, 0.f, 0.f);
    int j = 0;
    for (; j + 4 <= m; j += 4) {
        int n0 = adj[j], n1 = adj[j + 1], n2 = adj[j + 2], n3 = adj[j + 3];
        float4 a = h4[(size_t)n0 * (C / 4) + c4];
        float4 b = h4[(size_t)n1 * (C / 4) + c4];
        float4 d = h4[(size_t)n2 * (C / 4) + c4];
        float4 f = h4[(size_t)n3 * (C / 4) + c4];
        acc.x += a.x + b.x + d.x + f.x;
        acc.y += a.y + b.y + d.y + f.y;
        acc.z += a.z + b.z + d.z + f.z;
        acc.w += a.w + b.w + d.w + f.w;
    }
    for (; j < m; j++) {
        float4 a = h4[(size_t)adj[j] * (C / 4) + c4];
        acc.x += a.x; acc.y += a.y; acc.z += a.z; acc.w += a.w;
    }
    float inv = g_invDe[e];
    acc.x *= inv; acc.y *= inv; acc.z *= inv; acc.w *= inv;
    ((float4*)fte)[(size_t)e * (C / 4) + c4] = acc;
}

// node aggregation + bias + leaky relu + fused JAX-threefry dropout (float4)
template<int C>
__global__ void k_node_apply(const float* __restrict__ fte,
                             const float* __restrict__ bias,
                             float* __restrict__ out,
                             uint32_t dk0, uint32_t dk1) {
    int n = blockIdx.x;
    int c4 = threadIdx.x;
    int s = g_off_n[n], m = g_cnt_n[n];
    const int* adj = g_adj_n + s;
    const float4* f4 = (const float4*)fte;
    float4 acc = make_float4(0.f, 0.f, 0.f, 0.f);
    int j = 0;
    for (; j + 4 <= m; j += 4) {
        int e0 = adj[j], e1 = adj[j + 1], e2 = adj[j + 2], e3 = adj[j + 3];
        float4 a = f4[(size_t)e0 * (C / 4) + c4];
        float4 b = f4[(size_t)e1 * (C / 4) + c4];
        float4 d = f4[(size_t)e2 * (C / 4) + c4];
        float4 f = f4[(size_t)e3 * (C / 4) + c4];
        acc.x += a.x + b.x + d.x + f.x;
        acc.y += a.y + b.y + d.y + f.y;
        acc.z += a.z + b.z + d.z + f.z;
        acc.w += a.w + b.w + d.w + f.w;
    }
    for (; j < m; j++) {
        float4 a = f4[(size_t)adj[j] * (C / 4) + c4];
        acc.x += a.x; acc.y += a.y; acc.z += a.z; acc.w += a.w;
    }
    float inv = g_invDn[n];
    float4 bv = ((const float4*)bias)[c4];
    float v[4] = {acc.x * inv + bv.x, acc.y * inv + bv.y,
                  acc.z * inv + bv.z, acc.w * inv + bv.w};
    uint32_t base = (uint32_t)n * C + c4 * 4;
    #pragma unroll
    for (int q = 0; q < 4; q++) {
        float t = v[q];
        t = (t >= 0.f) ? t : 0.01f * t;          // leaky relu
        // JAX partitionable threefry: word = o0 ^ o1 of threefry(key, 0, idx)
        uint32_t o0, o1;
        threefry2x32(dk0, dk1, 0u, base + q, o0, o1);
        v[q] = (((o0 ^ o1) >> 31) == 0u) ? t * 2.0f : 0.0f;
    }
    ((float4*)out)[(size_t)n * (C / 4) + c4] = make_float4(v[0], v[1], v[2], v[3]);
}

// ---------------- dropmax (top-12 zeroed, JAX tie-break) + pooled sum -------
__global__ void k_dropmax(const float* __restrict__ h, float* __restrict__ feats,
                          float* __restrict__ pool) {
    __shared__ float s_pool[HID1];
    int t = threadIdx.x;
    if (t < HID1) s_pool[t] = 0.f;
    __syncthreads();
    int warp = t >> 5, lane = t & 31;
    int row = blockIdx.x * (blockDim.x >> 5) + warp;
    if (row < N_NODES) {
        float4 v4 = ((const float4*)(h + (size_t)row * HID1))[lane];
        float v[4] = {v4.x, v4.y, v4.z, v4.w};
        unsigned long long key[4];
        bool rem[4] = {false, false, false, false};
        #pragma unroll
        for (int j = 0; j < 4; j++) {
            uint32_t b = __float_as_uint(v[j]);
            uint32_t ord = (b & 0x80000000u) ? ~b : (b | 0x80000000u);
            key[j] = ((unsigned long long)ord << 32) |
                     (unsigned long long)(uint32_t)(127 - (lane * 4 + j));
        }
        for (int it = 0; it < 12; it++) {
            unsigned long long best = 0ull;
            #pragma unroll
            for (int j = 0; j < 4; j++) if (!rem[j] && key[j] > best) best = key[j];
            #pragma unroll
            for (int o = 16; o > 0; o >>= 1) {
                unsigned long long other = __shfl_xor_sync(0xffffffffu, best, o);
                if (other > best) best = other;
            }
            #pragma unroll
            for (int j = 0; j < 4; j++) if (key[j] == best) rem[j] = true;
        }
        #pragma unroll
        for (int j = 0; j < 4; j++) if (rem[j]) v[j] = 0.f;
        ((float4*)(feats + (size_t)row * HID1))[lane] =
            make_float4(v[0], v[1], v[2], v[3]);
        #pragma unroll
        for (int j = 0; j < 4; j++) atomicAdd(&s_pool[lane * 4 + j], v[j]);
    }
    __syncthreads();
    if (t < HID1) atomicAdd(&pool[t], s_pool[t]);
}

// ---------------- head: mean, fc, sigmoid ------------------------------------
__global__ void k_final(const float* __restrict__ Wfc, const float* __restrict__ bfc,
                        float* __restrict__ d_out) {
    __shared__ float p[HID1];
    int t = threadIdx.x;
    if (t < HID1) {
        float pv = g_pool[t] * (1.0f / (float)N_NODES);
        p[t] = pv;
        d_out[32 + (size_t)N_NODES * HID1 + t] = pv;   // feats_pool
    }
    __syncthreads();
    if (t < N_TGT) {
        float acc = bfc[t];
        #pragma unroll 8
        for (int c = 0; c < HID1; c++) acc += p[c] * Wfc[c * N_TGT + t];
        d_out[t] = 1.0f / (1.0f + expf(-acc));
    }
}

// ---------------- launch ------------------------------------------------------
extern "C" void kernel_launch(void* const* d_in, const int* in_sizes, int n_in,
                              void* d_out, int out_size) {
    const float* x   = (const float*)d_in[0];
    const int*   H   = (const int*)  d_in[1];
    const float* W0  = (const float*)d_in[2];
    const float* b0  = (const float*)d_in[3];
    const float* W1  = (const float*)d_in[4];
    const float* b1  = (const float*)d_in[5];
    const float* Wfc = (const float*)d_in[6];
    const float* bfc = (const float*)d_in[7];
    float* out = (float*)d_out;

    float *p_h, *p_fte, *p_hout, *p_pool;
    cudaGetSymbolAddress((void**)&p_h,    g_h);
    cudaGetSymbolAddress((void**)&p_fte,  g_fte);
    cudaGetSymbolAddress((void**)&p_hout, g_hout);
    cudaGetSymbolAddress((void**)&p_pool, g_pool);

    // JAX keys: base key(42) = (0,42); fold_in(key, i) = threefry(key, (0, i))
    uint32_t l0k0, l0k1, l1k0, l1k1;
    threefry2x32(0u, 42u, 0u, 0u, l0k0, l0k1);
    threefry2x32(0u, 42u, 0u, 1u, l1k0, l1k1);

    const int NBLK = (N_EDGES + 1023) / 1024;   // 49

    // degrees + CSR adjacency (linear schedule — round-5 config)
    k_zero     <<<196, 256>>>();
    k_degree   <<<(N_PAIRS + 255) / 256, 256>>>(H);
    k_scan_part<<<dim3(NBLK, 2), 1024>>>();
    k_scan_top <<<2, 64>>>();
    k_scan_add <<<dim3(NBLK, 2), 1024>>>();
    k_fill     <<<(N_PAIRS + 255) / 256, 256>>>(H);

    // ----- layer 0 -----
    k_gemm<<<dim3((N_NODES + 127) / 128, HID0 / 128), 256>>>(x, W0, p_h,
                                                             N_NODES, HID0, IN_CH);
    k_edge_gather<HID0><<<N_EDGES, HID0 / 4>>>(p_h, p_fte);
    k_node_apply<HID0><<<N_NODES, HID0 / 4>>>(p_fte, b0, p_hout, l0k0, l0k1);

    // ----- layer 1 -----
    k_gemm<<<dim3((N_NODES + 127) / 128, HID1 / 128), 256>>>(p_hout, W1, p_h,
                                                             N_NODES, HID1, HID0);
    k_edge_gather<HID1><<<N_EDGES, HID1 / 4>>>(p_h, p_fte);
    k_node_apply<HID1><<<N_NODES, HID1 / 4>>>(p_fte, b1, p_hout, l1k0, l1k1);

    // ----- dropmax + pool + head -----
    k_dropmax<<<(N_NODES + 7) / 8, 256>>>(p_hout, out + 32, p_pool);
    k_final<<<1, 128>>>(Wfc, bfc, out);
}

// round 9
// speedup vs baseline: 1.3766x; 1.0197x over previous
#include <cuda_runtime.h>
#include <stdint.h>

#define N_NODES 50000
#define N_EDGES 50000
#define N_PAIRS 800000
#define IN_CH   512
#define HID0    256
#define HID1    128
#define N_TGT   32

// ---------------- scratch (static device globals; no cudaMalloc allowed) ----
__device__ __align__(16) float g_h   [(size_t)N_NODES * HID0];
__device__ __align__(16) float g_fte [(size_t)N_EDGES * HID0];
__device__ __align__(16) float g_hout[(size_t)N_NODES * HID0];
__device__ float g_invDe[N_EDGES], g_invDn[N_NODES];
__device__ int   g_cnt_e[N_EDGES], g_cnt_n[N_NODES];
__device__ int   g_off_e[N_EDGES], g_off_n[N_NODES];
__device__ int   g_cur_e[N_EDGES], g_cur_n[N_NODES];
__device__ int   g_adj_e[N_PAIRS];
__device__ int   g_adj_n[N_PAIRS];
__device__ int   g_bsum[2][64];
__device__ float g_pool[HID1];

// ---------------- threefry2x32 (exact JAX semantics) ------------------------
__host__ __device__ __forceinline__ uint32_t rotl32(uint32_t x, int d) {
    return (x << d) | (x >> (32 - d));
}
__host__ __device__ __forceinline__ void threefry2x32(
    uint32_t k0, uint32_t k1, uint32_t x0, uint32_t x1,
    uint32_t& o0, uint32_t& o1)
{
    uint32_t k2 = k0 ^ k1 ^ 0x1BD11BDAu;
    x0 += k0; x1 += k1;
    x0 += x1; x1 = rotl32(x1,13); x1 ^= x0;
    x0 += x1; x1 = rotl32(x1,15); x1 ^= x0;
    x0 += x1; x1 = rotl32(x1,26); x1 ^= x0;
    x0 += x1; x1 = rotl32(x1, 6); x1 ^= x0;
    x0 += k1; x1 += k2 + 1u;
    x0 += x1; x1 = rotl32(x1,17); x1 ^= x0;
    x0 += x1; x1 = rotl32(x1,29); x1 ^= x0;
    x0 += x1; x1 = rotl32(x1,16); x1 ^= x0;
    x0 += x1; x1 = rotl32(x1,24); x1 ^= x0;
    x0 += k2; x1 += k0 + 2u;
    x0 += x1; x1 = rotl32(x1,13); x1 ^= x0;
    x0 += x1; x1 = rotl32(x1,15); x1 ^= x0;
    x0 += x1; x1 = rotl32(x1,26); x1 ^= x0;
    x0 += x1; x1 = rotl32(x1, 6); x1 ^= x0;
    x0 += k0; x1 += k1 + 3u;
    x0 += x1; x1 = rotl32(x1,17); x1 ^= x0;
    x0 += x1; x1 = rotl32(x1,29); x1 ^= x0;
    x0 += x1; x1 = rotl32(x1,16); x1 ^= x0;
    x0 += x1; x1 = rotl32(x1,24); x1 ^= x0;
    x0 += k1; x1 += k2 + 4u;
    x0 += x1; x1 = rotl32(x1,13); x1 ^= x0;
    x0 += x1; x1 = rotl32(x1,15); x1 ^= x0;
    x0 += x1; x1 = rotl32(x1,26); x1 ^= x0;
    x0 += x1; x1 = rotl32(x1, 6); x1 ^= x0;
    x0 += k2; x1 += k0 + 5u;
    o0 = x0; o1 = x1;
}

// ---------------- small setup kernels ---------------------------------------
__global__ void k_zero() {
    int i = blockIdx.x * blockDim.x + threadIdx.x;
    if (i < N_EDGES) g_cnt_e[i] = 0;
    if (i < N_NODES) g_cnt_n[i] = 0;
    if (i < HID1)    g_pool[i]  = 0.f;
}

__global__ void k_degree(const int* __restrict__ H) {
    int p = blockIdx.x * blockDim.x + threadIdx.x;
    if (p < N_PAIRS) {
        atomicAdd(&g_cnt_n[H[p]], 1);
        atomicAdd(&g_cnt_e[H[N_PAIRS + p]], 1);
    }
}

// ---------------- 3-phase parallel exclusive scan ----------------------------
__global__ void k_scan_part() {
    int arr = blockIdx.y;
    const int* cnt = arr ? g_cnt_n : g_cnt_e;
    int* off       = arr ? g_off_n : g_off_e;
    __shared__ int wsum[32];
    int i = blockIdx.x * 1024 + threadIdx.x;
    int lane = threadIdx.x & 31, w = threadIdx.x >> 5;
    int v = (i < N_EDGES) ? cnt[i] : 0;
    int x = v;
    #pragma unroll
    for (int o = 1; o < 32; o <<= 1) {
        int y = __shfl_up_sync(0xffffffffu, x, o);
        if (lane >= o) x += y;
    }
    if (lane == 31) wsum[w] = x;
    __syncthreads();
    if (w == 0) {
        int s = wsum[lane];
        #pragma unroll
        for (int o = 1; o < 32; o <<= 1) {
            int y = __shfl_up_sync(0xffffffffu, s, o);
            if (lane >= o) s += y;
        }
        wsum[lane] = s;
    }
    __syncthreads();
    int incl = x + ((w > 0) ? wsum[w - 1] : 0);
    if (i < N_EDGES) off[i] = incl - v;
    if (threadIdx.x == 1023) g_bsum[arr][blockIdx.x] = incl;
}

__global__ void k_scan_top() {
    int arr = blockIdx.x;
    __shared__ int s[64];
    int t = threadIdx.x;
    s[t] = (t < 49) ? g_bsum[arr][t] : 0;
    __syncthreads();
    #pragma unroll
    for (int o = 1; o < 64; o <<= 1) {
        int val = (t >= o) ? s[t - o] : 0;
        __syncthreads();
        s[t] += val;
        __syncthreads();
    }
    if (t < 49) g_bsum[arr][t] = s[t];
}

__global__ void k_scan_add() {
    int arr = blockIdx.y;
    int i = blockIdx.x * 1024 + threadIdx.x;
    if (i >= N_EDGES) return;
    int add = blockIdx.x ? g_bsum[arr][blockIdx.x - 1] : 0;
    if (arr == 0) {
        int o = g_off_e[i] + add;
        g_off_e[i] = o; g_cur_e[i] = o;
        g_invDe[i] = 1.0f / fmaxf((float)g_cnt_e[i], 1.0f);
    } else {
        int o = g_off_n[i] + add;
        g_off_n[i] = o; g_cur_n[i] = o;
        g_invDn[i] = 1.0f / fmaxf((float)g_cnt_n[i], 1.0f);
    }
}

__global__ void k_fill(const int* __restrict__ H) {
    int p = blockIdx.x * blockDim.x + threadIdx.x;
    if (p < N_PAIRS) {
        int n = H[p], e = H[N_PAIRS + p];
        g_adj_e[atomicAdd(&g_cur_e[e], 1)] = n;
        g_adj_n[atomicAdd(&g_cur_n[n], 1)] = e;
    }
}

// ---------------- SGEMM: FFMA2 + cp.async double-buffered pipeline ----------
#define FMA2(d, a, b) asm("fma.rn.f32x2 %0, %1, %2, %0;" : "+l"(d) : "l"(a), "l"(b))
#define BKT 16

__device__ __forceinline__ void cp16(uint32_t dst, const float* src) {
    asm volatile("cp.async.cg.shared.global [%0], [%1], 16;" :: "r"(dst), "l"(src));
}

__global__ void k_gemm(const float* __restrict__ A, const float* __restrict__ B,
                       float* __restrict__ C, int M, int N, int K) {
    __shared__ float As[2][128][BKT];    // raw row-major A tile
    __shared__ float Bs[2][BKT][132];    // row stride 528B (16B aligned)
    int tid = threadIdx.x;
    int bm = blockIdx.x * 128;
    int bn = blockIdx.y * 128;
    int tx = tid & 15, ty = tid >> 4;

    // A: thread loads 8 consecutive floats (2x16B) of row tid>>1, kcol (tid&1)*8
    int arow = tid >> 1, acol = (tid & 1) << 3;
    int grow = bm + arow; if (grow > M - 1) grow = M - 1;   // clamp (never stored)
    const float* Abase = A + (size_t)grow * K + acol;
    // B: thread loads 8 consecutive floats of tile-row tid>>4, col (tid&15)*8
    int brow = tid >> 4, bcol = (tid & 15) << 3;
    const float* Bbase = B + (size_t)brow * N + bn + bcol;

    uint32_t asA[2], asB[2];
    asA[0] = (uint32_t)__cvta_generic_to_shared(&As[0][arow][acol]);
    asA[1] = (uint32_t)__cvta_generic_to_shared(&As[1][arow][acol]);
    asB[0] = (uint32_t)__cvta_generic_to_shared(&Bs[0][brow][bcol]);
    asB[1] = (uint32_t)__cvta_generic_to_shared(&Bs[1][brow][bcol]);

    unsigned long long acc[8][4];
    #pragma unroll
    for (int i = 0; i < 8; i++)
        #pragma unroll
        for (int j = 0; j < 4; j++) acc[i][j] = 0ull;

    int T = K / BKT;
    // prologue: tile 0 -> buffer 0
    cp16(asA[0],      Abase);
    cp16(asA[0] + 16, Abase + 4);
    cp16(asB[0],      Bbase);
    cp16(asB[0] + 16, Bbase + 4);
    asm volatile("cp.async.commit_group;");

    for (int t = 0; t < T; t++) {
        int cur = t & 1;
        if (t + 1 < T) {                       // prefetch t+1 into other buffer
            int nxt = cur ^ 1;
            const float* an = Abase + (t + 1) * BKT;
            const float* bnp = Bbase + (size_t)(t + 1) * BKT * N;
            cp16(asA[nxt],      an);
            cp16(asA[nxt] + 16, an + 4);
            cp16(asB[nxt],      bnp);
            cp16(asB[nxt] + 16, bnp + 4);
            asm volatile("cp.async.commit_group;");
            asm volatile("cp.async.wait_group 1;");
        } else {
            asm volatile("cp.async.wait_group 0;");
        }
        __syncthreads();

        #pragma unroll
        for (int kk = 0; kk < BKT; kk++) {
            ulonglong2 b01 = *(const ulonglong2*)&Bs[cur][kk][tx * 8];
            ulonglong2 b23 = *(const ulonglong2*)&Bs[cur][kk][tx * 8 + 4];
            #pragma unroll
            for (int i = 0; i < 8; i++) {
                float a = As[cur][ty * 8 + i][kk];   // warp-broadcast scalar
                unsigned long long a2;
                asm("mov.b64 %0, {%1, %1};" : "=l"(a2) : "f"(a));
                FMA2(acc[i][0], a2, b01.x);
                FMA2(acc[i][1], a2, b01.y);
                FMA2(acc[i][2], a2, b23.x);
                FMA2(acc[i][3], a2, b23.y);
            }
        }
        __syncthreads();
    }

    #pragma unroll
    for (int i = 0; i < 8; i++) {
        int row = bm + ty * 8 + i;
        if (row < M) {
            float2 p0 = *(float2*)&acc[i][0];
            float2 p1 = *(float2*)&acc[i][1];
            float2 p2 = *(float2*)&acc[i][2];
            float2 p3 = *(float2*)&acc[i][3];
            float4* cp = (float4*)(C + (size_t)row * N + bn + tx * 8);
            cp[0] = make_float4(p0.x, p0.y, p1.x, p1.y);
            cp[1] = make_float4(p2.x, p2.y, p3.x, p3.y);
        }
    }
}

// ---------------- sparse gathers (CSR, float4-vectorized) --------------------
template<int C>
__global__ void k_edge_gather(const float* __restrict__ h, float* __restrict__ fte) {
    int e = blockIdx.x;
    int c4 = threadIdx.x;
    int s = g_off_e[e], m = g_cnt_e[e];
    const int* adj = g_adj_e + s;
    const float4* h4 = (const float4*)h;
    float4 acc = make_float4(0.f, 0.f, 0.f, 0.f);
    int j = 0;
    for (; j + 4 <= m; j += 4) {
        int n0 = adj[j], n1 = adj[j + 1], n2 = adj[j + 2], n3 = adj[j + 3];
        float4 a = h4[(size_t)n0 * (C / 4) + c4];
        float4 b = h4[(size_t)n1 * (C / 4) + c4];
        float4 d = h4[(size_t)n2 * (C / 4) + c4];
        float4 f = h4[(size_t)n3 * (C / 4) + c4];
        acc.x += a.x + b.x + d.x + f.x;
        acc.y += a.y + b.y + d.y + f.y;
        acc.z += a.z + b.z + d.z + f.z;
        acc.w += a.w + b.w + d.w + f.w;
    }
    for (; j < m; j++) {
        float4 a = h4[(size_t)adj[j] * (C / 4) + c4];
        acc.x += a.x; acc.y += a.y; acc.z += a.z; acc.w += a.w;
    }
    float inv = g_invDe[e];
    acc.x *= inv; acc.y *= inv; acc.z *= inv; acc.w *= inv;
    ((float4*)fte)[(size_t)e * (C / 4) + c4] = acc;
}

template<int C>
__global__ void k_node_apply(const float* __restrict__ fte,
                             const float* __restrict__ bias,
                             float* __restrict__ out,
                             uint32_t dk0, uint32_t dk1) {
    int n = blockIdx.x;
    int c4 = threadIdx.x;
    int s = g_off_n[n], m = g_cnt_n[n];
    const int* adj = g_adj_n + s;
    const float4* f4 = (const float4*)fte;
    float4 acc = make_float4(0.f, 0.f, 0.f, 0.f);
    int j = 0;
    for (; j + 4 <= m; j += 4) {
        int e0 = adj[j], e1 = adj[j + 1], e2 = adj[j + 2], e3 = adj[j + 3];
        float4 a = f4[(size_t)e0 * (C / 4) + c4];
        float4 b = f4[(size_t)e1 * (C / 4) + c4];
        float4 d = f4[(size_t)e2 * (C / 4) + c4];
        float4 f = f4[(size_t)e3 * (C / 4) + c4];
        acc.x += a.x + b.x + d.x + f.x;
        acc.y += a.y + b.y + d.y + f.y;
        acc.z += a.z + b.z + d.z + f.z;
        acc.w += a.w + b.w + d.w + f.w;
    }
    for (; j < m; j++) {
        float4 a = f4[(size_t)adj[j] * (C / 4) + c4];
        acc.x += a.x; acc.y += a.y; acc.z += a.z; acc.w += a.w;
    }
    float inv = g_invDn[n];
    float4 bv = ((const float4*)bias)[c4];
    float v[4] = {acc.x * inv + bv.x, acc.y * inv + bv.y,
                  acc.z * inv + bv.z, acc.w * inv + bv.w};
    uint32_t base = (uint32_t)n * C + c4 * 4;
    #pragma unroll
    for (int q = 0; q < 4; q++) {
        float t = v[q];
        t = (t >= 0.f) ? t : 0.01f * t;
        uint32_t o0, o1;
        threefry2x32(dk0, dk1, 0u, base + q, o0, o1);
        v[q] = (((o0 ^ o1) >> 31) == 0u) ? t * 2.0f : 0.0f;
    }
    ((float4*)out)[(size_t)n * (C / 4) + c4] = make_float4(v[0], v[1], v[2], v[3]);
}

// ---------------- dropmax (top-12 zeroed, JAX tie-break) + pooled sum -------
__global__ void k_dropmax(const float* __restrict__ h, float* __restrict__ feats,
                          float* __restrict__ pool) {
    __shared__ float s_pool[HID1];
    int t = threadIdx.x;
    if (t < HID1) s_pool[t] = 0.f;
    __syncthreads();
    int warp = t >> 5, lane = t & 31;
    int row = blockIdx.x * (blockDim.x >> 5) + warp;
    if (row < N_NODES) {
        float4 v4 = ((const float4*)(h + (size_t)row * HID1))[lane];
        float v[4] = {v4.x, v4.y, v4.z, v4.w};
        unsigned long long key[4];
        bool rem[4] = {false, false, false, false};
        #pragma unroll
        for (int j = 0; j < 4; j++) {
            uint32_t b = __float_as_uint(v[j]);
            uint32_t ord = (b & 0x80000000u) ? ~b : (b | 0x80000000u);
            key[j] = ((unsigned long long)ord << 32) |
                     (unsigned long long)(uint32_t)(127 - (lane * 4 + j));
        }
        for (int it = 0; it < 12; it++) {
            unsigned long long best = 0ull;
            #pragma unroll
            for (int j = 0; j < 4; j++) if (!rem[j] && key[j] > best) best = key[j];
            #pragma unroll
            for (int o = 16; o > 0; o >>= 1) {
                unsigned long long other = __shfl_xor_sync(0xffffffffu, best, o);
                if (other > best) best = other;
            }
            #pragma unroll
            for (int j = 0; j < 4; j++) if (key[j] == best) rem[j] = true;
        }
        #pragma unroll
        for (int j = 0; j < 4; j++) if (rem[j]) v[j] = 0.f;
        ((float4*)(feats + (size_t)row * HID1))[lane] =
            make_float4(v[0], v[1], v[2], v[3]);
        #pragma unroll
        for (int j = 0; j < 4; j++) atomicAdd(&s_pool[lane * 4 + j], v[j]);
    }
    __syncthreads();
    if (t < HID1) atomicAdd(&pool[t], s_pool[t]);
}

// ---------------- head: mean, fc, sigmoid ------------------------------------
__global__ void k_final(const float* __restrict__ Wfc, const float* __restrict__ bfc,
                        float* __restrict__ d_out) {
    __shared__ float p[HID1];
    int t = threadIdx.x;
    if (t < HID1) {
        float pv = g_pool[t] * (1.0f / (float)N_NODES);
        p[t] = pv;
        d_out[32 + (size_t)N_NODES * HID1 + t] = pv;
    }
    __syncthreads();
    if (t < N_TGT) {
        float acc = bfc[t];
        #pragma unroll 8
        for (int c = 0; c < HID1; c++) acc += p[c] * Wfc[c * N_TGT + t];
        d_out[t] = 1.0f / (1.0f + expf(-acc));
    }
}

// ---------------- launch ------------------------------------------------------
extern "C" void kernel_launch(void* const* d_in, const int* in_sizes, int n_in,
                              void* d_out, int out_size) {
    const float* x   = (const float*)d_in[0];
    const int*   H   = (const int*)  d_in[1];
    const float* W0  = (const float*)d_in[2];
    const float* b0  = (const float*)d_in[3];
    const float* W1  = (const float*)d_in[4];
    const float* b1  = (const float*)d_in[5];
    const float* Wfc = (const float*)d_in[6];
    const float* bfc = (const float*)d_in[7];
    float* out = (float*)d_out;

    float *p_h, *p_fte, *p_hout, *p_pool;
    cudaGetSymbolAddress((void**)&p_h,    g_h);
    cudaGetSymbolAddress((void**)&p_fte,  g_fte);
    cudaGetSymbolAddress((void**)&p_hout, g_hout);
    cudaGetSymbolAddress((void**)&p_pool, g_pool);

    uint32_t l0k0, l0k1, l1k0, l1k1;
    threefry2x32(0u, 42u, 0u, 0u, l0k0, l0k1);
    threefry2x32(0u, 42u, 0u, 1u, l1k0, l1k1);

    const int NBLK = (N_EDGES + 1023) / 1024;   // 49

    k_zero     <<<196, 256>>>();
    k_degree   <<<(N_PAIRS + 255) / 256, 256>>>(H);
    k_scan_part<<<dim3(NBLK, 2), 1024>>>();
    k_scan_top <<<2, 64>>>();
    k_scan_add <<<dim3(NBLK, 2), 1024>>>();
    k_fill     <<<(N_PAIRS + 255) / 256, 256>>>(H);

    // ----- layer 0 -----
    k_gemm<<<dim3((N_NODES + 127) / 128, HID0 / 128), 256>>>(x, W0, p_h,
                                                             N_NODES, HID0, IN_CH);
    k_edge_gather<HID0><<<N_EDGES, HID0 / 4>>>(p_h, p_fte);
    k_node_apply<HID0><<<N_NODES, HID0 / 4>>>(p_fte, b0, p_hout, l0k0, l0k1);

    // ----- layer 1 -----
    k_gemm<<<dim3((N_NODES + 127) / 128, HID1 / 128), 256>>>(p_hout, W1, p_h,
                                                             N_NODES, HID1, HID0);
    k_edge_gather<HID1><<<N_EDGES, HID1 / 4>>>(p_h, p_fte);
    k_node_apply<HID1><<<N_NODES, HID1 / 4>>>(p_fte, b1, p_hout, l1k0, l1k1);

    // ----- dropmax + pool + head -----
    k_dropmax<<<(N_NODES + 7) / 8, 256>>>(p_hout, out + 32, p_pool);
    k_final<<<1, 128>>>(Wfc, bfc, out);
}

// round 10
// speedup vs baseline: 1.3969x; 1.0147x over previous
#include <cuda_runtime.h>
#include <stdint.h>

#define N_NODES 50000
#define N_EDGES 50000
#define N_PAIRS 800000
#define IN_CH   512
#define HID0    256
#define HID1    128
#define N_TGT   32

// ---------------- scratch (static device globals; no cudaMalloc allowed) ----
__device__ __align__(16) float g_h   [(size_t)N_NODES * HID0];
__device__ __align__(16) float g_fte [(size_t)N_EDGES * HID0];
__device__ __align__(16) float g_hout[(size_t)N_NODES * HID0];
__device__ float g_invDe[N_EDGES], g_invDn[N_NODES];
__device__ int   g_cnt_e[N_EDGES], g_cnt_n[N_NODES];
__device__ int   g_off_e[N_EDGES], g_off_n[N_NODES];
__device__ int   g_cur_e[N_EDGES], g_cur_n[N_NODES];
__device__ int   g_adj_e[N_PAIRS];
__device__ int   g_adj_n[N_PAIRS];
__device__ int   g_bsum[2][64];
__device__ float g_pool[HID1];

// ---------------- threefry2x32 (exact JAX semantics) ------------------------
__host__ __device__ __forceinline__ uint32_t rotl32(uint32_t x, int d) {
    return (x << d) | (x >> (32 - d));
}
__host__ __device__ __forceinline__ void threefry2x32(
    uint32_t k0, uint32_t k1, uint32_t x0, uint32_t x1,
    uint32_t& o0, uint32_t& o1)
{
    uint32_t k2 = k0 ^ k1 ^ 0x1BD11BDAu;
    x0 += k0; x1 += k1;
    x0 += x1; x1 = rotl32(x1,13); x1 ^= x0;
    x0 += x1; x1 = rotl32(x1,15); x1 ^= x0;
    x0 += x1; x1 = rotl32(x1,26); x1 ^= x0;
    x0 += x1; x1 = rotl32(x1, 6); x1 ^= x0;
    x0 += k1; x1 += k2 + 1u;
    x0 += x1; x1 = rotl32(x1,17); x1 ^= x0;
    x0 += x1; x1 = rotl32(x1,29); x1 ^= x0;
    x0 += x1; x1 = rotl32(x1,16); x1 ^= x0;
    x0 += x1; x1 = rotl32(x1,24); x1 ^= x0;
    x0 += k2; x1 += k0 + 2u;
    x0 += x1; x1 = rotl32(x1,13); x1 ^= x0;
    x0 += x1; x1 = rotl32(x1,15); x1 ^= x0;
    x0 += x1; x1 = rotl32(x1,26); x1 ^= x0;
    x0 += x1; x1 = rotl32(x1, 6); x1 ^= x0;
    x0 += k0; x1 += k1 + 3u;
    x0 += x1; x1 = rotl32(x1,17); x1 ^= x0;
    x0 += x1; x1 = rotl32(x1,29); x1 ^= x0;
    x0 += x1; x1 = rotl32(x1,16); x1 ^= x0;
    x0 += x1; x1 = rotl32(x1,24); x1 ^= x0;
    x0 += k1; x1 += k2 + 4u;
    x0 += x1; x1 = rotl32(x1,13); x1 ^= x0;
    x0 += x1; x1 = rotl32(x1,15); x1 ^= x0;
    x0 += x1; x1 = rotl32(x1,26); x1 ^= x0;
    x0 += x1; x1 = rotl32(x1, 6); x1 ^= x0;
    x0 += k2; x1 += k0 + 5u;
    o0 = x0; o1 = x1;
}

// ---------------- small setup kernels ---------------------------------------
__global__ void k_zero() {
    int i = blockIdx.x * blockDim.x + threadIdx.x;
    if (i < N_EDGES) g_cnt_e[i] = 0;
    if (i < N_NODES) g_cnt_n[i] = 0;
    if (i < HID1)    g_pool[i]  = 0.f;
}

__global__ void k_degree(const int* __restrict__ H) {
    int p = blockIdx.x * blockDim.x + threadIdx.x;
    if (p < N_PAIRS) {
        atomicAdd(&g_cnt_n[H[p]], 1);
        atomicAdd(&g_cnt_e[H[N_PAIRS + p]], 1);
    }
}

// ---------------- 3-phase parallel exclusive scan ----------------------------
__global__ void k_scan_part() {
    int arr = blockIdx.y;
    const int* cnt = arr ? g_cnt_n : g_cnt_e;
    int* off       = arr ? g_off_n : g_off_e;
    __shared__ int wsum[32];
    int i = blockIdx.x * 1024 + threadIdx.x;
    int lane = threadIdx.x & 31, w = threadIdx.x >> 5;
    int v = (i < N_EDGES) ? cnt[i] : 0;
    int x = v;
    #pragma unroll
    for (int o = 1; o < 32; o <<= 1) {
        int y = __shfl_up_sync(0xffffffffu, x, o);
        if (lane >= o) x += y;
    }
    if (lane == 31) wsum[w] = x;
    __syncthreads();
    if (w == 0) {
        int s = wsum[lane];
        #pragma unroll
        for (int o = 1; o < 32; o <<= 1) {
            int y = __shfl_up_sync(0xffffffffu, s, o);
            if (lane >= o) s += y;
        }
        wsum[lane] = s;
    }
    __syncthreads();
    int incl = x + ((w > 0) ? wsum[w - 1] : 0);
    if (i < N_EDGES) off[i] = incl - v;
    if (threadIdx.x == 1023) g_bsum[arr][blockIdx.x] = incl;
}

__global__ void k_scan_top() {
    int arr = blockIdx.x;
    __shared__ int s[64];
    int t = threadIdx.x;
    s[t] = (t < 49) ? g_bsum[arr][t] : 0;
    __syncthreads();
    #pragma unroll
    for (int o = 1; o < 64; o <<= 1) {
        int val = (t >= o) ? s[t - o] : 0;
        __syncthreads();
        s[t] += val;
        __syncthreads();
    }
    if (t < 49) g_bsum[arr][t] = s[t];
}

__global__ void k_scan_add() {
    int arr = blockIdx.y;
    int i = blockIdx.x * 1024 + threadIdx.x;
    if (i >= N_EDGES) return;
    int add = blockIdx.x ? g_bsum[arr][blockIdx.x - 1] : 0;
    if (arr == 0) {
        int o = g_off_e[i] + add;
        g_off_e[i] = o; g_cur_e[i] = o;
        g_invDe[i] = 1.0f / fmaxf((float)g_cnt_e[i], 1.0f);
    } else {
        int o = g_off_n[i] + add;
        g_off_n[i] = o; g_cur_n[i] = o;
        g_invDn[i] = 1.0f / fmaxf((float)g_cnt_n[i], 1.0f);
    }
}

__global__ void k_fill(const int* __restrict__ H) {
    int p = blockIdx.x * blockDim.x + threadIdx.x;
    if (p < N_PAIRS) {
        int n = H[p], e = H[N_PAIRS + p];
        g_adj_e[atomicAdd(&g_cur_e[e], 1)] = n;
        g_adj_n[atomicAdd(&g_cur_n[n], 1)] = e;
    }
}

// ---------------- SGEMM: FFMA2 + cp.async double-buffered pipeline ----------
#define FMA2(d, a, b) asm("fma.rn.f32x2 %0, %1, %2, %0;" : "+l"(d) : "l"(a), "l"(b))
#define BKT 16

__device__ __forceinline__ void cp16(uint32_t dst, const float* src) {
    asm volatile("cp.async.cg.shared.global [%0], [%1], 16;" :: "r"(dst), "l"(src));
}

__global__ void k_gemm(const float* __restrict__ A, const float* __restrict__ B,
                       float* __restrict__ C, int M, int N, int K) {
    __shared__ float As[2][128][BKT];
    __shared__ float Bs[2][BKT][132];
    int tid = threadIdx.x;
    int bm = blockIdx.x * 128;
    int bn = blockIdx.y * 128;
    int tx = tid & 15, ty = tid >> 4;

    int arow = tid >> 1, acol = (tid & 1) << 3;
    int grow = bm + arow; if (grow > M - 1) grow = M - 1;
    const float* Abase = A + (size_t)grow * K + acol;
    int brow = tid >> 4, bcol = (tid & 15) << 3;
    const float* Bbase = B + (size_t)brow * N + bn + bcol;

    uint32_t asA[2], asB[2];
    asA[0] = (uint32_t)__cvta_generic_to_shared(&As[0][arow][acol]);
    asA[1] = (uint32_t)__cvta_generic_to_shared(&As[1][arow][acol]);
    asB[0] = (uint32_t)__cvta_generic_to_shared(&Bs[0][brow][bcol]);
    asB[1] = (uint32_t)__cvta_generic_to_shared(&Bs[1][brow][bcol]);

    unsigned long long acc[8][4];
    #pragma unroll
    for (int i = 0; i < 8; i++)
        #pragma unroll
        for (int j = 0; j < 4; j++) acc[i][j] = 0ull;

    int T = K / BKT;
    cp16(asA[0],      Abase);
    cp16(asA[0] + 16, Abase + 4);
    cp16(asB[0],      Bbase);
    cp16(asB[0] + 16, Bbase + 4);
    asm volatile("cp.async.commit_group;");

    for (int t = 0; t < T; t++) {
        int cur = t & 1;
        if (t + 1 < T) {
            int nxt = cur ^ 1;
            const float* an = Abase + (t + 1) * BKT;
            const float* bnp = Bbase + (size_t)(t + 1) * BKT * N;
            cp16(asA[nxt],      an);
            cp16(asA[nxt] + 16, an + 4);
            cp16(asB[nxt],      bnp);
            cp16(asB[nxt] + 16, bnp + 4);
            asm volatile("cp.async.commit_group;");
            asm volatile("cp.async.wait_group 1;");
        } else {
            asm volatile("cp.async.wait_group 0;");
        }
        __syncthreads();

        #pragma unroll
        for (int kk = 0; kk < BKT; kk++) {
            ulonglong2 b01 = *(const ulonglong2*)&Bs[cur][kk][tx * 8];
            ulonglong2 b23 = *(const ulonglong2*)&Bs[cur][kk][tx * 8 + 4];
            #pragma unroll
            for (int i = 0; i < 8; i++) {
                float a = As[cur][ty * 8 + i][kk];
                unsigned long long a2;
                asm("mov.b64 %0, {%1, %1};" : "=l"(a2) : "f"(a));
                FMA2(acc[i][0], a2, b01.x);
                FMA2(acc[i][1], a2, b01.y);
                FMA2(acc[i][2], a2, b23.x);
                FMA2(acc[i][3], a2, b23.y);
            }
        }
        __syncthreads();
    }

    #pragma unroll
    for (int i = 0; i < 8; i++) {
        int row = bm + ty * 8 + i;
        if (row < M) {
            float2 p0 = *(float2*)&acc[i][0];
            float2 p1 = *(float2*)&acc[i][1];
            float2 p2 = *(float2*)&acc[i][2];
            float2 p3 = *(float2*)&acc[i][3];
            float4* cp = (float4*)(C + (size_t)row * N + bn + tx * 8);
            cp[0] = make_float4(p0.x, p0.y, p1.x, p1.y);
            cp[1] = make_float4(p2.x, p2.y, p3.x, p3.y);
        }
    }
}

// ---------------- sparse gathers (CSR, float4-vectorized) --------------------
template<int C>
__global__ void k_edge_gather(const float* __restrict__ h, float* __restrict__ fte) {
    int e = blockIdx.x;
    int c4 = threadIdx.x;
    int s = g_off_e[e], m = g_cnt_e[e];
    const int* adj = g_adj_e + s;
    const float4* h4 = (const float4*)h;
    float4 acc = make_float4(0.f, 0.f, 0.f, 0.f);
    int j = 0;
    for (; j + 4 <= m; j += 4) {
        int n0 = adj[j], n1 = adj[j + 1], n2 = adj[j + 2], n3 = adj[j + 3];
        float4 a = h4[(size_t)n0 * (C / 4) + c4];
        float4 b = h4[(size_t)n1 * (C / 4) + c4];
        float4 d = h4[(size_t)n2 * (C / 4) + c4];
        float4 f = h4[(size_t)n3 * (C / 4) + c4];
        acc.x += a.x + b.x + d.x + f.x;
        acc.y += a.y + b.y + d.y + f.y;
        acc.z += a.z + b.z + d.z + f.z;
        acc.w += a.w + b.w + d.w + f.w;
    }
    for (; j < m; j++) {
        float4 a = h4[(size_t)adj[j] * (C / 4) + c4];
        acc.x += a.x; acc.y += a.y; acc.z += a.z; acc.w += a.w;
    }
    float inv = g_invDe[e];
    acc.x *= inv; acc.y *= inv; acc.z *= inv; acc.w *= inv;
    ((float4*)fte)[(size_t)e * (C / 4) + c4] = acc;
}

// node aggregation + bias + leaky relu + fused threefry dropout (layer 0)
template<int C>
__global__ void k_node_apply(const float* __restrict__ fte,
                             const float* __restrict__ bias,
                             float* __restrict__ out,
                             uint32_t dk0, uint32_t dk1) {
    int n = blockIdx.x;
    int c4 = threadIdx.x;
    int s = g_off_n[n], m = g_cnt_n[n];
    const int* adj = g_adj_n + s;
    const float4* f4 = (const float4*)fte;
    float4 acc = make_float4(0.f, 0.f, 0.f, 0.f);
    int j = 0;
    for (; j + 4 <= m; j += 4) {
        int e0 = adj[j], e1 = adj[j + 1], e2 = adj[j + 2], e3 = adj[j + 3];
        float4 a = f4[(size_t)e0 * (C / 4) + c4];
        float4 b = f4[(size_t)e1 * (C / 4) + c4];
        float4 d = f4[(size_t)e2 * (C / 4) + c4];
        float4 f = f4[(size_t)e3 * (C / 4) + c4];
        acc.x += a.x + b.x + d.x + f.x;
        acc.y += a.y + b.y + d.y + f.y;
        acc.z += a.z + b.z + d.z + f.z;
        acc.w += a.w + b.w + d.w + f.w;
    }
    for (; j < m; j++) {
        float4 a = f4[(size_t)adj[j] * (C / 4) + c4];
        acc.x += a.x; acc.y += a.y; acc.z += a.z; acc.w += a.w;
    }
    float inv = g_invDn[n];
    float4 bv = ((const float4*)bias)[c4];
    float v[4] = {acc.x * inv + bv.x, acc.y * inv + bv.y,
                  acc.z * inv + bv.z, acc.w * inv + bv.w};
    uint32_t base = (uint32_t)n * C + c4 * 4;
    #pragma unroll
    for (int q = 0; q < 4; q++) {
        float t = v[q];
        t = (t >= 0.f) ? t : 0.01f * t;
        uint32_t o0, o1;
        threefry2x32(dk0, dk1, 0u, base + q, o0, o1);
        v[q] = (((o0 ^ o1) >> 31) == 0u) ? t * 2.0f : 0.0f;
    }
    ((float4*)out)[(size_t)n * (C / 4) + c4] = make_float4(v[0], v[1], v[2], v[3]);
}

// ---- layer-1 node apply FUSED with dropmax + pool (one node per warp) -------
__global__ void k_node_dropmax(const float* __restrict__ fte,
                               const float* __restrict__ bias,
                               float* __restrict__ feats,
                               float* __restrict__ pool,
                               uint32_t dk0, uint32_t dk1) {
    __shared__ float s_pool[HID1];
    int t = threadIdx.x;
    if (t < HID1) s_pool[t] = 0.f;
    __syncthreads();
    int warp = t >> 5, lane = t & 31;
    int n = blockIdx.x * 8 + warp;
    if (n < N_NODES) {
        // ---- aggregate over incident edges (float4 per lane, 128 ch/warp) --
        int s = g_off_n[n], m = g_cnt_n[n];
        const int* adj = g_adj_n + s;
        const float4* f4 = (const float4*)fte;
        float4 acc = make_float4(0.f, 0.f, 0.f, 0.f);
        int j = 0;
        for (; j + 4 <= m; j += 4) {
            int e0 = adj[j], e1 = adj[j + 1], e2 = adj[j + 2], e3 = adj[j + 3];
            float4 a = f4[(size_t)e0 * (HID1 / 4) + lane];
            float4 b = f4[(size_t)e1 * (HID1 / 4) + lane];
            float4 d = f4[(size_t)e2 * (HID1 / 4) + lane];
            float4 f = f4[(size_t)e3 * (HID1 / 4) + lane];
            acc.x += a.x + b.x + d.x + f.x;
            acc.y += a.y + b.y + d.y + f.y;
            acc.z += a.z + b.z + d.z + f.z;
            acc.w += a.w + b.w + d.w + f.w;
        }
        for (; j < m; j++) {
            float4 a = f4[(size_t)adj[j] * (HID1 / 4) + lane];
            acc.x += a.x; acc.y += a.y; acc.z += a.z; acc.w += a.w;
        }
        float inv = g_invDn[n];
        float4 bv = ((const float4*)bias)[lane];
        float v[4] = {acc.x * inv + bv.x, acc.y * inv + bv.y,
                      acc.z * inv + bv.z, acc.w * inv + bv.w};
        // ---- leaky relu + JAX threefry dropout -----------------------------
        uint32_t base = (uint32_t)n * HID1 + lane * 4;
        #pragma unroll
        for (int q = 0; q < 4; q++) {
            float x = v[q];
            x = (x >= 0.f) ? x : 0.01f * x;
            uint32_t o0, o1;
            threefry2x32(dk0, dk1, 0u, base + q, o0, o1);
            v[q] = (((o0 ^ o1) >> 31) == 0u) ? x * 2.0f : 0.0f;
        }
        // ---- dropmax: zero top-12 (JAX top_k tie-break: lower index wins) --
        unsigned long long key[4];
        bool rem[4] = {false, false, false, false};
        #pragma unroll
        for (int q = 0; q < 4; q++) {
            uint32_t b = __float_as_uint(v[q]);
            uint32_t ord = (b & 0x80000000u) ? ~b : (b | 0x80000000u);
            key[q] = ((unsigned long long)ord << 32) |
                     (unsigned long long)(uint32_t)(127 - (lane * 4 + q));
        }
        for (int it = 0; it < 12; it++) {
            unsigned long long best = 0ull;
            #pragma unroll
            for (int q = 0; q < 4; q++) if (!rem[q] && key[q] > best) best = key[q];
            #pragma unroll
            for (int o = 16; o > 0; o >>= 1) {
                unsigned long long other = __shfl_xor_sync(0xffffffffu, best, o);
                if (other > best) best = other;
            }
            #pragma unroll
            for (int q = 0; q < 4; q++) if (key[q] == best) rem[q] = true;
        }
        #pragma unroll
        for (int q = 0; q < 4; q++) if (rem[q]) v[q] = 0.f;
        ((float4*)feats)[(size_t)n * (HID1 / 4) + lane] =
            make_float4(v[0], v[1], v[2], v[3]);
        #pragma unroll
        for (int q = 0; q < 4; q++) atomicAdd(&s_pool[lane * 4 + q], v[q]);
    }
    __syncthreads();
    if (t < HID1) atomicAdd(&pool[t], s_pool[t]);
}

// ---------------- head: mean, fc, sigmoid ------------------------------------
__global__ void k_final(const float* __restrict__ Wfc, const float* __restrict__ bfc,
                        float* __restrict__ d_out) {
    __shared__ float p[HID1];
    int t = threadIdx.x;
    if (t < HID1) {
        float pv = g_pool[t] * (1.0f / (float)N_NODES);
        p[t] = pv;
        d_out[32 + (size_t)N_NODES * HID1 + t] = pv;
    }
    __syncthreads();
    if (t < N_TGT) {
        float acc = bfc[t];
        #pragma unroll 8
        for (int c = 0; c < HID1; c++) acc += p[c] * Wfc[c * N_TGT + t];
        d_out[t] = 1.0f / (1.0f + expf(-acc));
    }
}

// ---------------- launch ------------------------------------------------------
extern "C" void kernel_launch(void* const* d_in, const int* in_sizes, int n_in,
                              void* d_out, int out_size) {
    const float* x   = (const float*)d_in[0];
    const int*   H   = (const int*)  d_in[1];
    const float* W0  = (const float*)d_in[2];
    const float* b0  = (const float*)d_in[3];
    const float* W1  = (const float*)d_in[4];
    const float* b1  = (const float*)d_in[5];
    const float* Wfc = (const float*)d_in[6];
    const float* bfc = (const float*)d_in[7];
    float* out = (float*)d_out;

    float *p_h, *p_fte, *p_hout, *p_pool;
    cudaGetSymbolAddress((void**)&p_h,    g_h);
    cudaGetSymbolAddress((void**)&p_fte,  g_fte);
    cudaGetSymbolAddress((void**)&p_hout, g_hout);
    cudaGetSymbolAddress((void**)&p_pool, g_pool);

    uint32_t l0k0, l0k1, l1k0, l1k1;
    threefry2x32(0u, 42u, 0u, 0u, l0k0, l0k1);
    threefry2x32(0u, 42u, 0u, 1u, l1k0, l1k1);

    const int NBLK = (N_EDGES + 1023) / 1024;   // 49

    // NOTE: gemm0 is hoisted to launch index 3 (it depends only on x/W0) so
    // ncu's fixed launch-index capture profiles the dominant kernel.
    k_zero     <<<196, 256>>>();                                           // 0
    k_degree   <<<(N_PAIRS + 255) / 256, 256>>>(H);                        // 1
    k_scan_part<<<dim3(NBLK, 2), 1024>>>();                                // 2
    k_gemm<<<dim3((N_NODES + 127) / 128, HID0 / 128), 256>>>(x, W0, p_h,   // 3
                                                             N_NODES, HID0, IN_CH);
    k_scan_top <<<2, 64>>>();                                              // 4
    k_scan_add <<<dim3(NBLK, 2), 1024>>>();                                // 5
    k_fill     <<<(N_PAIRS + 255) / 256, 256>>>(H);                        // 6

    // ----- layer 0 (rest) -----
    k_edge_gather<HID0><<<N_EDGES, HID0 / 4>>>(p_h, p_fte);
    k_node_apply<HID0><<<N_NODES, HID0 / 4>>>(p_fte, b0, p_hout, l0k0, l0k1);

    // ----- layer 1 -----
    k_gemm<<<dim3((N_NODES + 127) / 128, HID1 / 128), 256>>>(p_hout, W1, p_h,
                                                             N_NODES, HID1, HID0);
    k_edge_gather<HID1><<<N_EDGES, HID1 / 4>>>(p_h, p_fte);

    // ----- fused: node apply + leaky + dropout + dropmax + pool -----
    k_node_dropmax<<<(N_NODES + 7) / 8, 256>>>(p_fte, b1, out + 32, p_pool,
                                               l1k0, l1k1);
    k_final<<<1, 128>>>(Wfc, bfc, out);
}

// round 11
// speedup vs baseline: 1.4673x; 1.0504x over previous
#include <cuda_runtime.h>
#include <stdint.h>

#define N_NODES 50000
#define N_EDGES 50000
#define N_PAIRS 800000
#define IN_CH   512
#define HID0    256
#define HID1    128
#define N_TGT   32

// ---------------- scratch (static device globals; no cudaMalloc allowed) ----
__device__ __align__(16) float g_h   [(size_t)N_NODES * HID0];
__device__ __align__(16) float g_fte [(size_t)N_EDGES * HID0];
__device__ __align__(16) float g_hout[(size_t)N_NODES * HID0];
__device__ float g_invDe[N_EDGES], g_invDn[N_NODES];
__device__ int   g_cnt_e[N_EDGES], g_cnt_n[N_NODES];
__device__ int   g_off_e[N_EDGES], g_off_n[N_NODES];
__device__ int   g_cur_e[N_EDGES], g_cur_n[N_NODES];
__device__ int   g_adj_e[N_PAIRS];
__device__ int   g_adj_n[N_PAIRS];
__device__ int   g_bsum[2][64];
__device__ float g_pool[HID1];

// ---------------- threefry2x32 (exact JAX semantics) ------------------------
__host__ __device__ __forceinline__ uint32_t rotl32(uint32_t x, int d) {
    return (x << d) | (x >> (32 - d));
}
__host__ __device__ __forceinline__ void threefry2x32(
    uint32_t k0, uint32_t k1, uint32_t x0, uint32_t x1,
    uint32_t& o0, uint32_t& o1)
{
    uint32_t k2 = k0 ^ k1 ^ 0x1BD11BDAu;
    x0 += k0; x1 += k1;
    x0 += x1; x1 = rotl32(x1,13); x1 ^= x0;
    x0 += x1; x1 = rotl32(x1,15); x1 ^= x0;
    x0 += x1; x1 = rotl32(x1,26); x1 ^= x0;
    x0 += x1; x1 = rotl32(x1, 6); x1 ^= x0;
    x0 += k1; x1 += k2 + 1u;
    x0 += x1; x1 = rotl32(x1,17); x1 ^= x0;
    x0 += x1; x1 = rotl32(x1,29); x1 ^= x0;
    x0 += x1; x1 = rotl32(x1,16); x1 ^= x0;
    x0 += x1; x1 = rotl32(x1,24); x1 ^= x0;
    x0 += k2; x1 += k0 + 2u;
    x0 += x1; x1 = rotl32(x1,13); x1 ^= x0;
    x0 += x1; x1 = rotl32(x1,15); x1 ^= x0;
    x0 += x1; x1 = rotl32(x1,26); x1 ^= x0;
    x0 += x1; x1 = rotl32(x1, 6); x1 ^= x0;
    x0 += k0; x1 += k1 + 3u;
    x0 += x1; x1 = rotl32(x1,17); x1 ^= x0;
    x0 += x1; x1 = rotl32(x1,29); x1 ^= x0;
    x0 += x1; x1 = rotl32(x1,16); x1 ^= x0;
    x0 += x1; x1 = rotl32(x1,24); x1 ^= x0;
    x0 += k1; x1 += k2 + 4u;
    x0 += x1; x1 = rotl32(x1,13); x1 ^= x0;
    x0 += x1; x1 = rotl32(x1,15); x1 ^= x0;
    x0 += x1; x1 = rotl32(x1,26); x1 ^= x0;
    x0 += x1; x1 = rotl32(x1, 6); x1 ^= x0;
    x0 += k2; x1 += k0 + 5u;
    o0 = x0; o1 = x1;
}

// ---------------- small setup kernels ---------------------------------------
__global__ void k_zero() {
    int i = blockIdx.x * blockDim.x + threadIdx.x;
    if (i < N_EDGES) g_cnt_e[i] = 0;
    if (i < N_NODES) g_cnt_n[i] = 0;
    if (i < HID1)    g_pool[i]  = 0.f;
}

__global__ void k_degree(const int* __restrict__ H) {
    int p = blockIdx.x * blockDim.x + threadIdx.x;
    if (p < N_PAIRS) {
        atomicAdd(&g_cnt_n[H[p]], 1);
        atomicAdd(&g_cnt_e[H[N_PAIRS + p]], 1);
    }
}

// ---------------- 3-phase parallel exclusive scan ----------------------------
__global__ void k_scan_part() {
    int arr = blockIdx.y;
    const int* cnt = arr ? g_cnt_n : g_cnt_e;
    int* off       = arr ? g_off_n : g_off_e;
    __shared__ int wsum[32];
    int i = blockIdx.x * 1024 + threadIdx.x;
    int lane = threadIdx.x & 31, w = threadIdx.x >> 5;
    int v = (i < N_EDGES) ? cnt[i] : 0;
    int x = v;
    #pragma unroll
    for (int o = 1; o < 32; o <<= 1) {
        int y = __shfl_up_sync(0xffffffffu, x, o);
        if (lane >= o) x += y;
    }
    if (lane == 31) wsum[w] = x;
    __syncthreads();
    if (w == 0) {
        int s = wsum[lane];
        #pragma unroll
        for (int o = 1; o < 32; o <<= 1) {
            int y = __shfl_up_sync(0xffffffffu, s, o);
            if (lane >= o) s += y;
        }
        wsum[lane] = s;
    }
    __syncthreads();
    int incl = x + ((w > 0) ? wsum[w - 1] : 0);
    if (i < N_EDGES) off[i] = incl - v;
    if (threadIdx.x == 1023) g_bsum[arr][blockIdx.x] = incl;
}

__global__ void k_scan_top() {
    int arr = blockIdx.x;
    __shared__ int s[64];
    int t = threadIdx.x;
    s[t] = (t < 49) ? g_bsum[arr][t] : 0;
    __syncthreads();
    #pragma unroll
    for (int o = 1; o < 64; o <<= 1) {
        int val = (t >= o) ? s[t - o] : 0;
        __syncthreads();
        s[t] += val;
        __syncthreads();
    }
    if (t < 49) g_bsum[arr][t] = s[t];
}

__global__ void k_scan_add() {
    int arr = blockIdx.y;
    int i = blockIdx.x * 1024 + threadIdx.x;
    if (i >= N_EDGES) return;
    int add = blockIdx.x ? g_bsum[arr][blockIdx.x - 1] : 0;
    if (arr == 0) {
        int o = g_off_e[i] + add;
        g_off_e[i] = o; g_cur_e[i] = o;
        g_invDe[i] = 1.0f / fmaxf((float)g_cnt_e[i], 1.0f);
    } else {
        int o = g_off_n[i] + add;
        g_off_n[i] = o; g_cur_n[i] = o;
        g_invDn[i] = 1.0f / fmaxf((float)g_cnt_n[i], 1.0f);
    }
}

__global__ void k_fill(const int* __restrict__ H) {
    int p = blockIdx.x * blockDim.x + threadIdx.x;
    if (p < N_PAIRS) {
        int n = H[p], e = H[N_PAIRS + p];
        g_adj_e[atomicAdd(&g_cur_e[e], 1)] = n;
        g_adj_n[atomicAdd(&g_cur_n[n], 1)] = e;
    }
}

// ---------------- SGEMM: FFMA2 + cp.async + 2 blocks/SM ---------------------
#define FMA2(d, a, b) asm("fma.rn.f32x2 %0, %1, %2, %0;" : "+l"(d) : "l"(a), "l"(b))
#define BKT 16

__device__ __forceinline__ void cp16(uint32_t dst, const float* src) {
    asm volatile("cp.async.cg.shared.global [%0], [%1], 16;" :: "r"(dst), "l"(src));
}

__global__ void __launch_bounds__(256, 2)
k_gemm(const float* __restrict__ A, const float* __restrict__ B,
       float* __restrict__ C, int M, int N, int K) {
    __shared__ float As[2][128][BKT];
    __shared__ float Bs[2][BKT][132];
    int tid = threadIdx.x;
    int bm = blockIdx.x * 128;
    int bn = blockIdx.y * 128;
    int tx = tid & 15, ty = tid >> 4;

    int arow = tid >> 1, acol = (tid & 1) << 3;
    int grow = bm + arow; if (grow > M - 1) grow = M - 1;
    const float* Abase = A + (size_t)grow * K + acol;
    int brow = tid >> 4, bcol = (tid & 15) << 3;
    const float* Bbase = B + (size_t)brow * N + bn + bcol;

    uint32_t asA[2], asB[2];
    asA[0] = (uint32_t)__cvta_generic_to_shared(&As[0][arow][acol]);
    asA[1] = (uint32_t)__cvta_generic_to_shared(&As[1][arow][acol]);
    asB[0] = (uint32_t)__cvta_generic_to_shared(&Bs[0][brow][bcol]);
    asB[1] = (uint32_t)__cvta_generic_to_shared(&Bs[1][brow][bcol]);

    unsigned long long acc[8][4];
    #pragma unroll
    for (int i = 0; i < 8; i++)
        #pragma unroll
        for (int j = 0; j < 4; j++) acc[i][j] = 0ull;

    int T = K / BKT;
    cp16(asA[0],      Abase);
    cp16(asA[0] + 16, Abase + 4);
    cp16(asB[0],      Bbase);
    cp16(asB[0] + 16, Bbase + 4);
    asm volatile("cp.async.commit_group;");

    for (int t = 0; t < T; t++) {
        int cur = t & 1;
        if (t + 1 < T) {
            int nxt = cur ^ 1;
            const float* an = Abase + (t + 1) * BKT;
            const float* bnp = Bbase + (size_t)(t + 1) * BKT * N;
            cp16(asA[nxt],      an);
            cp16(asA[nxt] + 16, an + 4);
            cp16(asB[nxt],      bnp);
            cp16(asB[nxt] + 16, bnp + 4);
            asm volatile("cp.async.commit_group;");
            asm volatile("cp.async.wait_group 1;");
        } else {
            asm volatile("cp.async.wait_group 0;");
        }
        __syncthreads();

        #pragma unroll
        for (int kk = 0; kk < BKT; kk += 2) {
            // cache A for this kk-pair: 8 rows x float2 (LDS.64, broadcast)
            float2 ap[8];
            #pragma unroll
            for (int i = 0; i < 8; i++)
                ap[i] = *(const float2*)&As[cur][ty * 8 + i][kk];

            ulonglong2 b01 = *(const ulonglong2*)&Bs[cur][kk][tx * 8];
            ulonglong2 b23 = *(const ulonglong2*)&Bs[cur][kk][tx * 8 + 4];
            #pragma unroll
            for (int i = 0; i < 8; i++) {
                unsigned long long a2;
                asm("mov.b64 %0, {%1, %1};" : "=l"(a2) : "f"(ap[i].x));
                FMA2(acc[i][0], a2, b01.x);
                FMA2(acc[i][1], a2, b01.y);
                FMA2(acc[i][2], a2, b23.x);
                FMA2(acc[i][3], a2, b23.y);
            }
            b01 = *(const ulonglong2*)&Bs[cur][kk + 1][tx * 8];
            b23 = *(const ulonglong2*)&Bs[cur][kk + 1][tx * 8 + 4];
            #pragma unroll
            for (int i = 0; i < 8; i++) {
                unsigned long long a2;
                asm("mov.b64 %0, {%1, %1};" : "=l"(a2) : "f"(ap[i].y));
                FMA2(acc[i][0], a2, b01.x);
                FMA2(acc[i][1], a2, b01.y);
                FMA2(acc[i][2], a2, b23.x);
                FMA2(acc[i][3], a2, b23.y);
            }
        }
        __syncthreads();
    }

    #pragma unroll
    for (int i = 0; i < 8; i++) {
        int row = bm + ty * 8 + i;
        if (row < M) {
            float2 p0 = *(float2*)&acc[i][0];
            float2 p1 = *(float2*)&acc[i][1];
            float2 p2 = *(float2*)&acc[i][2];
            float2 p3 = *(float2*)&acc[i][3];
            float4* cp = (float4*)(C + (size_t)row * N + bn + tx * 8);
            cp[0] = make_float4(p0.x, p0.y, p1.x, p1.y);
            cp[1] = make_float4(p2.x, p2.y, p3.x, p3.y);
        }
    }
}

// ---------------- sparse gathers (CSR, float4-vectorized) --------------------
template<int C>
__global__ void k_edge_gather(const float* __restrict__ h, float* __restrict__ fte) {
    int e = blockIdx.x;
    int c4 = threadIdx.x;
    int s = g_off_e[e], m = g_cnt_e[e];
    const int* adj = g_adj_e + s;
    const float4* h4 = (const float4*)h;
    float4 acc = make_float4(0.f, 0.f, 0.f, 0.f);
    int j = 0;
    for (; j + 4 <= m; j += 4) {
        int n0 = adj[j], n1 = adj[j + 1], n2 = adj[j + 2], n3 = adj[j + 3];
        float4 a = h4[(size_t)n0 * (C / 4) + c4];
        float4 b = h4[(size_t)n1 * (C / 4) + c4];
        float4 d = h4[(size_t)n2 * (C / 4) + c4];
        float4 f = h4[(size_t)n3 * (C / 4) + c4];
        acc.x += a.x + b.x + d.x + f.x;
        acc.y += a.y + b.y + d.y + f.y;
        acc.z += a.z + b.z + d.z + f.z;
        acc.w += a.w + b.w + d.w + f.w;
    }
    for (; j < m; j++) {
        float4 a = h4[(size_t)adj[j] * (C / 4) + c4];
        acc.x += a.x; acc.y += a.y; acc.z += a.z; acc.w += a.w;
    }
    float inv = g_invDe[e];
    acc.x *= inv; acc.y *= inv; acc.z *= inv; acc.w *= inv;
    ((float4*)fte)[(size_t)e * (C / 4) + c4] = acc;
}

// node aggregation + bias + leaky relu + fused threefry dropout (layer 0)
template<int C>
__global__ void k_node_apply(const float* __restrict__ fte,
                             const float* __restrict__ bias,
                             float* __restrict__ out,
                             uint32_t dk0, uint32_t dk1) {
    int n = blockIdx.x;
    int c4 = threadIdx.x;
    int s = g_off_n[n], m = g_cnt_n[n];
    const int* adj = g_adj_n + s;
    const float4* f4 = (const float4*)fte;
    float4 acc = make_float4(0.f, 0.f, 0.f, 0.f);
    int j = 0;
    for (; j + 4 <= m; j += 4) {
        int e0 = adj[j], e1 = adj[j + 1], e2 = adj[j + 2], e3 = adj[j + 3];
        float4 a = f4[(size_t)e0 * (C / 4) + c4];
        float4 b = f4[(size_t)e1 * (C / 4) + c4];
        float4 d = f4[(size_t)e2 * (C / 4) + c4];
        float4 f = f4[(size_t)e3 * (C / 4) + c4];
        acc.x += a.x + b.x + d.x + f.x;
        acc.y += a.y + b.y + d.y + f.y;
        acc.z += a.z + b.z + d.z + f.z;
        acc.w += a.w + b.w + d.w + f.w;
    }
    for (; j < m; j++) {
        float4 a = f4[(size_t)adj[j] * (C / 4) + c4];
        acc.x += a.x; acc.y += a.y; acc.z += a.z; acc.w += a.w;
    }
    float inv = g_invDn[n];
    float4 bv = ((const float4*)bias)[c4];
    float v[4] = {acc.x * inv + bv.x, acc.y * inv + bv.y,
                  acc.z * inv + bv.z, acc.w * inv + bv.w};
    uint32_t base = (uint32_t)n * C + c4 * 4;
    #pragma unroll
    for (int q = 0; q < 4; q++) {
        float t = v[q];
        t = (t >= 0.f) ? t : 0.01f * t;
        uint32_t o0, o1;
        threefry2x32(dk0, dk1, 0u, base + q, o0, o1);
        v[q] = (((o0 ^ o1) >> 31) == 0u) ? t * 2.0f : 0.0f;
    }
    ((float4*)out)[(size_t)n * (C / 4) + c4] = make_float4(v[0], v[1], v[2], v[3]);
}

// ---- layer-1 node apply FUSED with dropmax + pool (one node per warp) -------
__global__ void k_node_dropmax(const float* __restrict__ fte,
                               const float* __restrict__ bias,
                               float* __restrict__ feats,
                               float* __restrict__ pool,
                               uint32_t dk0, uint32_t dk1) {
    __shared__ float s_pool[HID1];
    int t = threadIdx.x;
    if (t < HID1) s_pool[t] = 0.f;
    __syncthreads();
    int warp = t >> 5, lane = t & 31;
    int n = blockIdx.x * 8 + warp;
    if (n < N_NODES) {
        int s = g_off_n[n], m = g_cnt_n[n];
        const int* adj = g_adj_n + s;
        const float4* f4 = (const float4*)fte;
        float4 acc = make_float4(0.f, 0.f, 0.f, 0.f);
        int j = 0;
        for (; j + 4 <= m; j += 4) {
            int e0 = adj[j], e1 = adj[j + 1], e2 = adj[j + 2], e3 = adj[j + 3];
            float4 a = f4[(size_t)e0 * (HID1 / 4) + lane];
            float4 b = f4[(size_t)e1 * (HID1 / 4) + lane];
            float4 d = f4[(size_t)e2 * (HID1 / 4) + lane];
            float4 f = f4[(size_t)e3 * (HID1 / 4) + lane];
            acc.x += a.x + b.x + d.x + f.x;
            acc.y += a.y + b.y + d.y + f.y;
            acc.z += a.z + b.z + d.z + f.z;
            acc.w += a.w + b.w + d.w + f.w;
        }
        for (; j < m; j++) {
            float4 a = f4[(size_t)adj[j] * (HID1 / 4) + lane];
            acc.x += a.x; acc.y += a.y; acc.z += a.z; acc.w += a.w;
        }
        float inv = g_invDn[n];
        float4 bv = ((const float4*)bias)[lane];
        float v[4] = {acc.x * inv + bv.x, acc.y * inv + bv.y,
                      acc.z * inv + bv.z, acc.w * inv + bv.w};
        uint32_t base = (uint32_t)n * HID1 + lane * 4;
        #pragma unroll
        for (int q = 0; q < 4; q++) {
            float x = v[q];
            x = (x >= 0.f) ? x : 0.01f * x;
            uint32_t o0, o1;
            threefry2x32(dk0, dk1, 0u, base + q, o0, o1);
            v[q] = (((o0 ^ o1) >> 31) == 0u) ? x * 2.0f : 0.0f;
        }
        unsigned long long key[4];
        bool rem[4] = {false, false, false, false};
        #pragma unroll
        for (int q = 0; q < 4; q++) {
            uint32_t b = __float_as_uint(v[q]);
            uint32_t ord = (b & 0x80000000u) ? ~b : (b | 0x80000000u);
            key[q] = ((unsigned long long)ord << 32) |
                     (unsigned long long)(uint32_t)(127 - (lane * 4 + q));
        }
        for (int it = 0; it < 12; it++) {
            unsigned long long best = 0ull;
            #pragma unroll
            for (int q = 0; q < 4; q++) if (!rem[q] && key[q] > best) best = key[q];
            #pragma unroll
            for (int o = 16; o > 0; o >>= 1) {
                unsigned long long other = __shfl_xor_sync(0xffffffffu, best, o);
                if (other > best) best = other;
            }
            #pragma unroll
            for (int q = 0; q < 4; q++) if (key[q] == best) rem[q] = true;
        }
        #pragma unroll
        for (int q = 0; q < 4; q++) if (rem[q]) v[q] = 0.f;
        ((float4*)feats)[(size_t)n * (HID1 / 4) + lane] =
            make_float4(v[0], v[1], v[2], v[3]);
        #pragma unroll
        for (int q = 0; q < 4; q++) atomicAdd(&s_pool[lane * 4 + q], v[q]);
    }
    __syncthreads();
    if (t < HID1) atomicAdd(&pool[t], s_pool[t]);
}

// ---------------- head: mean, fc, sigmoid ------------------------------------
__global__ void k_final(const float* __restrict__ Wfc, const float* __restrict__ bfc,
                        float* __restrict__ d_out) {
    __shared__ float p[HID1];
    int t = threadIdx.x;
    if (t < HID1) {
        float pv = g_pool[t] * (1.0f / (float)N_NODES);
        p[t] = pv;
        d_out[32 + (size_t)N_NODES * HID1 + t] = pv;
    }
    __syncthreads();
    if (t < N_TGT) {
        float acc = bfc[t];
        #pragma unroll 8
        for (int c = 0; c < HID1; c++) acc += p[c] * Wfc[c * N_TGT + t];
        d_out[t] = 1.0f / (1.0f + expf(-acc));
    }
}

// ---------------- launch ------------------------------------------------------
extern "C" void kernel_launch(void* const* d_in, const int* in_sizes, int n_in,
                              void* d_out, int out_size) {
    const float* x   = (const float*)d_in[0];
    const int*   H   = (const int*)  d_in[1];
    const float* W0  = (const float*)d_in[2];
    const float* b0  = (const float*)d_in[3];
    const float* W1  = (const float*)d_in[4];
    const float* b1  = (const float*)d_in[5];
    const float* Wfc = (const float*)d_in[6];
    const float* bfc = (const float*)d_in[7];
    float* out = (float*)d_out;

    float *p_h, *p_fte, *p_hout, *p_pool;
    cudaGetSymbolAddress((void**)&p_h,    g_h);
    cudaGetSymbolAddress((void**)&p_fte,  g_fte);
    cudaGetSymbolAddress((void**)&p_hout, g_hout);
    cudaGetSymbolAddress((void**)&p_pool, g_pool);

    uint32_t l0k0, l0k1, l1k0, l1k1;
    threefry2x32(0u, 42u, 0u, 0u, l0k0, l0k1);
    threefry2x32(0u, 42u, 0u, 1u, l1k0, l1k1);

    const int NBLK = (N_EDGES + 1023) / 1024;   // 49

    // gemm0 kept at launch index 3 so ncu profiles the dominant kernel.
    k_zero     <<<196, 256>>>();                                           // 0
    k_degree   <<<(N_PAIRS + 255) / 256, 256>>>(H);                        // 1
    k_scan_part<<<dim3(NBLK, 2), 1024>>>();                                // 2
    k_gemm<<<dim3((N_NODES + 127) / 128, HID0 / 128), 256>>>(x, W0, p_h,   // 3
                                                             N_NODES, HID0, IN_CH);
    k_scan_top <<<2, 64>>>();                                              // 4
    k_scan_add <<<dim3(NBLK, 2), 1024>>>();                                // 5
    k_fill     <<<(N_PAIRS + 255) / 256, 256>>>(H);                        // 6

    // ----- layer 0 (rest) -----
    k_edge_gather<HID0><<<N_EDGES, HID0 / 4>>>(p_h, p_fte);
    k_node_apply<HID0><<<N_NODES, HID0 / 4>>>(p_fte, b0, p_hout, l0k0, l0k1);

    // ----- layer 1 -----
    k_gemm<<<dim3((N_NODES + 127) / 128, HID1 / 128), 256>>>(p_hout, W1, p_h,
                                                             N_NODES, HID1, HID0);
    k_edge_gather<HID1><<<N_EDGES, HID1 / 4>>>(p_h, p_fte);

    // ----- fused: node apply + leaky + dropout + dropmax + pool -----
    k_node_dropmax<<<(N_NODES + 7) / 8, 256>>>(p_fte, b1, out + 32, p_pool,
                                               l1k0, l1k1);
    k_final<<<1, 128>>>(Wfc, bfc, out);
}

// round 14
// speedup vs baseline: 1.5481x; 1.0551x over previous
#include <cuda_runtime.h>
#include <stdint.h>

#define N_NODES 50000
#define N_EDGES 50000
#define N_PAIRS 800000
#define IN_CH   512
#define HID0    256
#define HID1    128
#define N_TGT   32

// ---------------- scratch (static device globals; no cudaMalloc allowed) ----
__device__ __align__(16) float g_h   [(size_t)N_NODES * HID0];
__device__ __align__(16) float g_fte [(size_t)N_EDGES * HID0];
__device__ __align__(16) float g_hout[(size_t)N_NODES * HID0];
__device__ float g_invDe[N_EDGES], g_invDn[N_NODES];
__device__ int   g_cnt_e[N_EDGES], g_cnt_n[N_NODES];
__device__ int   g_off_e[N_EDGES], g_off_n[N_NODES];
__device__ int   g_cur_e[N_EDGES], g_cur_n[N_NODES];
__device__ int   g_adj_e[N_PAIRS];
__device__ int   g_adj_n[N_PAIRS];
__device__ int   g_bsum[2][64];
__device__ float g_pool[HID1];

// ---------------- threefry2x32 (exact JAX semantics) ------------------------
__host__ __device__ __forceinline__ uint32_t rotl32(uint32_t x, int d) {
    return (x << d) | (x >> (32 - d));
}
__host__ __device__ __forceinline__ void threefry2x32(
    uint32_t k0, uint32_t k1, uint32_t x0, uint32_t x1,
    uint32_t& o0, uint32_t& o1)
{
    uint32_t k2 = k0 ^ k1 ^ 0x1BD11BDAu;
    x0 += k0; x1 += k1;
    x0 += x1; x1 = rotl32(x1,13); x1 ^= x0;
    x0 += x1; x1 = rotl32(x1,15); x1 ^= x0;
    x0 += x1; x1 = rotl32(x1,26); x1 ^= x0;
    x0 += x1; x1 = rotl32(x1, 6); x1 ^= x0;
    x0 += k1; x1 += k2 + 1u;
    x0 += x1; x1 = rotl32(x1,17); x1 ^= x0;
    x0 += x1; x1 = rotl32(x1,29); x1 ^= x0;
    x0 += x1; x1 = rotl32(x1,16); x1 ^= x0;
    x0 += x1; x1 = rotl32(x1,24); x1 ^= x0;
    x0 += k2; x1 += k0 + 2u;
    x0 += x1; x1 = rotl32(x1,13); x1 ^= x0;
    x0 += x1; x1 = rotl32(x1,15); x1 ^= x0;
    x0 += x1; x1 = rotl32(x1,26); x1 ^= x0;
    x0 += x1; x1 = rotl32(x1, 6); x1 ^= x0;
    x0 += k0; x1 += k1 + 3u;
    x0 += x1; x1 = rotl32(x1,17); x1 ^= x0;
    x0 += x1; x1 = rotl32(x1,29); x1 ^= x0;
    x0 += x1; x1 = rotl32(x1,16); x1 ^= x0;
    x0 += x1; x1 = rotl32(x1,24); x1 ^= x0;
    x0 += k1; x1 += k2 + 4u;
    x0 += x1; x1 = rotl32(x1,13); x1 ^= x0;
    x0 += x1; x1 = rotl32(x1,15); x1 ^= x0;
    x0 += x1; x1 = rotl32(x1,26); x1 ^= x0;
    x0 += x1; x1 = rotl32(x1, 6); x1 ^= x0;
    x0 += k2; x1 += k0 + 5u;
    o0 = x0; o1 = x1;
}

// ---------------- small setup kernels ---------------------------------------
__global__ void k_zero() {
    int i = blockIdx.x * blockDim.x + threadIdx.x;
    if (i < N_EDGES) g_cnt_e[i] = 0;
    if (i < N_NODES) g_cnt_n[i] = 0;
    if (i < HID1)    g_pool[i]  = 0.f;
}

__global__ void k_degree(const int* __restrict__ H) {
    int p = blockIdx.x * blockDim.x + threadIdx.x;
    if (p < N_PAIRS) {
        atomicAdd(&g_cnt_n[H[p]], 1);
        atomicAdd(&g_cnt_e[H[N_PAIRS + p]], 1);
    }
}

// ---------------- 3-phase parallel exclusive scan ----------------------------
__global__ void k_scan_part() {
    int arr = blockIdx.y;
    const int* cnt = arr ? g_cnt_n : g_cnt_e;
    int* off       = arr ? g_off_n : g_off_e;
    __shared__ int wsum[32];
    int i = blockIdx.x * 1024 + threadIdx.x;
    int lane = threadIdx.x & 31, w = threadIdx.x >> 5;
    int v = (i < N_EDGES) ? cnt[i] : 0;
    int x = v;
    #pragma unroll
    for (int o = 1; o < 32; o <<= 1) {
        int y = __shfl_up_sync(0xffffffffu, x, o);
        if (lane >= o) x += y;
    }
    if (lane == 31) wsum[w] = x;
    __syncthreads();
    if (w == 0) {
        int s = wsum[lane];
        #pragma unroll
        for (int o = 1; o < 32; o <<= 1) {
            int y = __shfl_up_sync(0xffffffffu, s, o);
            if (lane >= o) s += y;
        }
        wsum[lane] = s;
    }
    __syncthreads();
    int incl = x + ((w > 0) ? wsum[w - 1] : 0);
    if (i < N_EDGES) off[i] = incl - v;
    if (threadIdx.x == 1023) g_bsum[arr][blockIdx.x] = incl;
}

__global__ void k_scan_top() {
    int arr = blockIdx.x;
    __shared__ int s[64];
    int t = threadIdx.x;
    s[t] = (t < 49) ? g_bsum[arr][t] : 0;
    __syncthreads();
    #pragma unroll
    for (int o = 1; o < 64; o <<= 1) {
        int val = (t >= o) ? s[t - o] : 0;
        __syncthreads();
        s[t] += val;
        __syncthreads();
    }
    if (t < 49) g_bsum[arr][t] = s[t];
}

__global__ void k_scan_add() {
    int arr = blockIdx.y;
    int i = blockIdx.x * 1024 + threadIdx.x;
    if (i >= N_EDGES) return;
    int add = blockIdx.x ? g_bsum[arr][blockIdx.x - 1] : 0;
    if (arr == 0) {
        int o = g_off_e[i] + add;
        g_off_e[i] = o; g_cur_e[i] = o;
        g_invDe[i] = 1.0f / fmaxf((float)g_cnt_e[i], 1.0f);
    } else {
        int o = g_off_n[i] + add;
        g_off_n[i] = o; g_cur_n[i] = o;
        g_invDn[i] = 1.0f / fmaxf((float)g_cnt_n[i], 1.0f);
    }
}

__global__ void k_fill(const int* __restrict__ H) {
    int p = blockIdx.x * blockDim.x + threadIdx.x;
    if (p < N_PAIRS) {
        int n = H[p], e = H[N_PAIRS + p];
        g_adj_e[atomicAdd(&g_cur_e[e], 1)] = n;
        g_adj_n[atomicAdd(&g_cur_n[n], 1)] = e;
    }
}

// ---------------- SGEMM: 16x4 micro-tile, transposed-A broadcast ------------
// Warp = 16 rows x 128 cols; A tile stored transposed [kk][row] so each warp's
// 16 A values per kk are one 64B broadcast region (4 LDS.128, 1 wavefront each).
// B via cp.async double buffer; A via LDG->STS (transpose on store).
#define FMA2(d, a, b) asm("fma.rn.f32x2 %0, %1, %2, %0;" : "+l"(d) : "l"(a), "l"(b))
#define BKT 16

__device__ __forceinline__ void cp16(uint32_t dst, const float* src) {
    asm volatile("cp.async.cg.shared.global [%0], [%1], 16;" :: "r"(dst), "l"(src));
}

__global__ void __launch_bounds__(256, 2)
k_gemm(const float* __restrict__ A, const float* __restrict__ B,
       float* __restrict__ C, int M, int N, int K) {
    __shared__ float At[2][BKT][136];    // transposed A: [kk][row], stride 544B
    __shared__ float Bs[2][BKT][132];
    int tid = threadIdx.x;
    int bm = blockIdx.x * 128;
    int bn = blockIdx.y * 128;
    int warp = tid >> 5, lane = tid & 31;

    // A fill: thread loads 8 floats along K of one row, stores transposed
    int arow = tid >> 1, acol = (tid & 1) << 3;
    int grow = bm + arow; if (grow > M - 1) grow = M - 1;  // clamp, never stored
    const float* Abase = A + (size_t)grow * K + acol;
    // B fill via cp.async
    int brow = tid >> 4, bcol = (tid & 15) << 3;
    const float* Bbase = B + (size_t)brow * N + bn + bcol;
    uint32_t asB[2];
    asB[0] = (uint32_t)__cvta_generic_to_shared(&Bs[0][brow][bcol]);
    asB[1] = (uint32_t)__cvta_generic_to_shared(&Bs[1][brow][bcol]);

    unsigned long long acc[16][2];
    #pragma unroll
    for (int r = 0; r < 16; r++) { acc[r][0] = 0ull; acc[r][1] = 0ull; }

    int T = K / BKT;

    // prologue: tile 0
    float4 av0 = *(const float4*)(Abase);
    float4 av1 = *(const float4*)(Abase + 4);
    cp16(asB[0],      Bbase);
    cp16(asB[0] + 16, Bbase + 4);
    asm volatile("cp.async.commit_group;");
    At[0][acol + 0][arow] = av0.x; At[0][acol + 1][arow] = av0.y;
    At[0][acol + 2][arow] = av0.z; At[0][acol + 3][arow] = av0.w;
    At[0][acol + 4][arow] = av1.x; At[0][acol + 5][arow] = av1.y;
    At[0][acol + 6][arow] = av1.z; At[0][acol + 7][arow] = av1.w;
    asm volatile("cp.async.wait_group 0;");
    __syncthreads();

    for (int t = 0; t < T; t++) {
        int cur = t & 1, nxt = cur ^ 1;
        if (t + 1 < T) {
            av0 = *(const float4*)(Abase + (t + 1) * BKT);
            av1 = *(const float4*)(Abase + (t + 1) * BKT + 4);
            const float* bp = Bbase + (size_t)(t + 1) * BKT * N;
            cp16(asB[nxt],      bp);
            cp16(asB[nxt] + 16, bp + 4);
            asm volatile("cp.async.commit_group;");
        }

        const float* atw = &At[cur][0][warp * 16];
        #pragma unroll
        for (int kk = 0; kk < BKT; kk++) {
            float a[16];
            *(float4*)&a[0]  = *(const float4*)(atw + kk * 136);
            *(float4*)&a[4]  = *(const float4*)(atw + kk * 136 + 4);
            *(float4*)&a[8]  = *(const float4*)(atw + kk * 136 + 8);
            *(float4*)&a[12] = *(const float4*)(atw + kk * 136 + 12);
            ulonglong2 bb = *(const ulonglong2*)&Bs[cur][kk][lane * 4];
            #pragma unroll
            for (int r = 0; r < 16; r++) {
                unsigned long long a2;
                asm("mov.b64 %0, {%1, %1};" : "=l"(a2) : "f"(a[r]));
                FMA2(acc[r][0], a2, bb.x);
                FMA2(acc[r][1], a2, bb.y);
            }
        }

        if (t + 1 < T) {
            At[nxt][acol + 0][arow] = av0.x; At[nxt][acol + 1][arow] = av0.y;
            At[nxt][acol + 2][arow] = av0.z; At[nxt][acol + 3][arow] = av0.w;
            At[nxt][acol + 4][arow] = av1.x; At[nxt][acol + 5][arow] = av1.y;
            At[nxt][acol + 6][arow] = av1.z; At[nxt][acol + 7][arow] = av1.w;
            asm volatile("cp.async.wait_group 0;");
        }
        __syncthreads();
    }

    #pragma unroll
    for (int r = 0; r < 16; r++) {
        int row = bm + warp * 16 + r;
        if (row < M) {
            float2 p0 = *(float2*)&acc[r][0];
            float2 p1 = *(float2*)&acc[r][1];
            *(float4*)(C + (size_t)row * N + bn + lane * 4) =
                make_float4(p0.x, p0.y, p1.x, p1.y);
        }
    }
}

// ---------------- sparse gathers (CSR, float4-vectorized) --------------------
template<int C>
__global__ void k_edge_gather(const float* __restrict__ h, float* __restrict__ fte) {
    int e = blockIdx.x;
    int c4 = threadIdx.x;
    int s = g_off_e[e], m = g_cnt_e[e];
    const int* adj = g_adj_e + s;
    const float4* h4 = (const float4*)h;
    float4 acc = make_float4(0.f, 0.f, 0.f, 0.f);
    int j = 0;
    for (; j + 4 <= m; j += 4) {
        int n0 = adj[j], n1 = adj[j + 1], n2 = adj[j + 2], n3 = adj[j + 3];
        float4 a = h4[(size_t)n0 * (C / 4) + c4];
        float4 b = h4[(size_t)n1 * (C / 4) + c4];
        float4 d = h4[(size_t)n2 * (C / 4) + c4];
        float4 f = h4[(size_t)n3 * (C / 4) + c4];
        acc.x += a.x + b.x + d.x + f.x;
        acc.y += a.y + b.y + d.y + f.y;
        acc.z += a.z + b.z + d.z + f.z;
        acc.w += a.w + b.w + d.w + f.w;
    }
    for (; j < m; j++) {
        float4 a = h4[(size_t)adj[j] * (C / 4) + c4];
        acc.x += a.x; acc.y += a.y; acc.z += a.z; acc.w += a.w;
    }
    float inv = g_invDe[e];
    acc.x *= inv; acc.y *= inv; acc.z *= inv; acc.w *= inv;
    ((float4*)fte)[(size_t)e * (C / 4) + c4] = acc;
}

// node aggregation + bias + leaky relu + fused threefry dropout (layer 0)
template<int C>
__global__ void k_node_apply(const float* __restrict__ fte,
                             const float* __restrict__ bias,
                             float* __restrict__ out,
                             uint32_t dk0, uint32_t dk1) {
    int n = blockIdx.x;
    int c4 = threadIdx.x;
    int s = g_off_n[n], m = g_cnt_n[n];
    const int* adj = g_adj_n + s;
    const float4* f4 = (const float4*)fte;
    float4 acc = make_float4(0.f, 0.f, 0.f, 0.f);
    int j = 0;
    for (; j + 4 <= m; j += 4) {
        int e0 = adj[j], e1 = adj[j + 1], e2 = adj[j + 2], e3 = adj[j + 3];
        float4 a = f4[(size_t)e0 * (C / 4) + c4];
        float4 b = f4[(size_t)e1 * (C / 4) + c4];
        float4 d = f4[(size_t)e2 * (C / 4) + c4];
        float4 f = f4[(size_t)e3 * (C / 4) + c4];
        acc.x += a.x + b.x + d.x + f.x;
        acc.y += a.y + b.y + d.y + f.y;
        acc.z += a.z + b.z + d.z + f.z;
        acc.w += a.w + b.w + d.w + f.w;
    }
    for (; j < m; j++) {
        float4 a = f4[(size_t)adj[j] * (C / 4) + c4];
        acc.x += a.x; acc.y += a.y; acc.z += a.z; acc.w += a.w;
    }
    float inv = g_invDn[n];
    float4 bv = ((const float4*)bias)[c4];
    float v[4] = {acc.x * inv + bv.x, acc.y * inv + bv.y,
                  acc.z * inv + bv.z, acc.w * inv + bv.w};
    uint32_t base = (uint32_t)n * C + c4 * 4;
    #pragma unroll
    for (int q = 0; q < 4; q++) {
        float t = v[q];
        t = (t >= 0.f) ? t : 0.01f * t;
        uint32_t o0, o1;
        threefry2x32(dk0, dk1, 0u, base + q, o0, o1);
        v[q] = (((o0 ^ o1) >> 31) == 0u) ? t * 2.0f : 0.0f;
    }
    ((float4*)out)[(size_t)n * (C / 4) + c4] = make_float4(v[0], v[1], v[2], v[3]);
}

// ---- layer-1 node apply FUSED with dropmax + pool (one node per warp) -------
__global__ void k_node_dropmax(const float* __restrict__ fte,
                               const float* __restrict__ bias,
                               float* __restrict__ feats,
                               float* __restrict__ pool,
                               uint32_t dk0, uint32_t dk1) {
    __shared__ float s_pool[HID1];
    int t = threadIdx.x;
    if (t < HID1) s_pool[t] = 0.f;
    __syncthreads();
    int warp = t >> 5, lane = t & 31;
    int n = blockIdx.x * 8 + warp;
    if (n < N_NODES) {
        int s = g_off_n[n], m = g_cnt_n[n];
        const int* adj = g_adj_n + s;
        const float4* f4 = (const float4*)fte;
        float4 acc = make_float4(0.f, 0.f, 0.f, 0.f);
        int j = 0;
        for (; j + 4 <= m; j += 4) {
            int e0 = adj[j], e1 = adj[j + 1], e2 = adj[j + 2], e3 = adj[j + 3];
            float4 a = f4[(size_t)e0 * (HID1 / 4) + lane];
            float4 b = f4[(size_t)e1 * (HID1 / 4) + lane];
            float4 d = f4[(size_t)e2 * (HID1 / 4) + lane];
            float4 f = f4[(size_t)e3 * (HID1 / 4) + lane];
            acc.x += a.x + b.x + d.x + f.x;
            acc.y += a.y + b.y + d.y + f.y;
            acc.z += a.z + b.z + d.z + f.z;
            acc.w += a.w + b.w + d.w + f.w;
        }
        for (; j < m; j++) {
            float4 a = f4[(size_t)adj[j] * (HID1 / 4) + lane];
            acc.x += a.x; acc.y += a.y; acc.z += a.z; acc.w += a.w;
        }
        float inv = g_invDn[n];
        float4 bv = ((const float4*)bias)[lane];
        float v[4] = {acc.x * inv + bv.x, acc.y * inv + bv.y,
                      acc.z * inv + bv.z, acc.w * inv + bv.w};
        uint32_t base = (uint32_t)n * HID1 + lane * 4;
        #pragma unroll
        for (int q = 0; q < 4; q++) {
            float x = v[q];
            x = (x >= 0.f) ? x : 0.01f * x;
            uint32_t o0, o1;
            threefry2x32(dk0, dk1, 0u, base + q, o0, o1);
            v[q] = (((o0 ^ o1) >> 31) == 0u) ? x * 2.0f : 0.0f;
        }
        unsigned long long key[4];
        bool rem[4] = {false, false, false, false};
        #pragma unroll
        for (int q = 0; q < 4; q++) {
            uint32_t b = __float_as_uint(v[q]);
            uint32_t ord = (b & 0x80000000u) ? ~b : (b | 0x80000000u);
            key[q] = ((unsigned long long)ord << 32) |
                     (unsigned long long)(uint32_t)(127 - (lane * 4 + q));
        }
        for (int it = 0; it < 12; it++) {
            unsigned long long best = 0ull;
            #pragma unroll
            for (int q = 0; q < 4; q++) if (!rem[q] && key[q] > best) best = key[q];
            #pragma unroll
            for (int o = 16; o > 0; o >>= 1) {
                unsigned long long other = __shfl_xor_sync(0xffffffffu, best, o);
                if (other > best) best = other;
            }
            #pragma unroll
            for (int q = 0; q < 4; q++) if (key[q] == best) rem[q] = true;
        }
        #pragma unroll
        for (int q = 0; q < 4; q++) if (rem[q]) v[q] = 0.f;
        ((float4*)feats)[(size_t)n * (HID1 / 4) + lane] =
            make_float4(v[0], v[1], v[2], v[3]);
        #pragma unroll
        for (int q = 0; q < 4; q++) atomicAdd(&s_pool[lane * 4 + q], v[q]);
    }
    __syncthreads();
    if (t < HID1) atomicAdd(&pool[t], s_pool[t]);
}

// ---------------- head: mean, fc, sigmoid ------------------------------------
__global__ void k_final(const float* __restrict__ Wfc, const float* __restrict__ bfc,
                        float* __restrict__ d_out) {
    __shared__ float p[HID1];
    int t = threadIdx.x;
    if (t < HID1) {
        float pv = g_pool[t] * (1.0f / (float)N_NODES);
        p[t] = pv;
        d_out[32 + (size_t)N_NODES * HID1 + t] = pv;
    }
    __syncthreads();
    if (t < N_TGT) {
        float acc = bfc[t];
        #pragma unroll 8
        for (int c = 0; c < HID1; c++) acc += p[c] * Wfc[c * N_TGT + t];
        d_out[t] = 1.0f / (1.0f + expf(-acc));
    }
}

// ---------------- launch ------------------------------------------------------
extern "C" void kernel_launch(void* const* d_in, const int* in_sizes, int n_in,
                              void* d_out, int out_size) {
    const float* x   = (const float*)d_in[0];
    const int*   H   = (const int*)  d_in[1];
    const float* W0  = (const float*)d_in[2];
    const float* b0  = (const float*)d_in[3];
    const float* W1  = (const float*)d_in[4];
    const float* b1  = (const float*)d_in[5];
    const float* Wfc = (const float*)d_in[6];
    const float* bfc = (const float*)d_in[7];
    float* out = (float*)d_out;

    float *p_h, *p_fte, *p_hout, *p_pool;
    cudaGetSymbolAddress((void**)&p_h,    g_h);
    cudaGetSymbolAddress((void**)&p_fte,  g_fte);
    cudaGetSymbolAddress((void**)&p_hout, g_hout);
    cudaGetSymbolAddress((void**)&p_pool, g_pool);

    uint32_t l0k0, l0k1, l1k0, l1k1;
    threefry2x32(0u, 42u, 0u, 0u, l0k0, l0k1);
    threefry2x32(0u, 42u, 0u, 1u, l1k0, l1k1);

    const int NBLK = (N_EDGES + 1023) / 1024;   // 49

    // gemm0 kept at launch index 3 so ncu profiles the dominant kernel.
    k_zero     <<<196, 256>>>();                                           // 0
    k_degree   <<<(N_PAIRS + 255) / 256, 256>>>(H);                        // 1
    k_scan_part<<<dim3(NBLK, 2), 1024>>>();                                // 2
    k_gemm<<<dim3((N_NODES + 127) / 128, HID0 / 128), 256>>>(x, W0, p_h,   // 3
                                                             N_NODES, HID0, IN_CH);
    k_scan_top <<<2, 64>>>();                                              // 4
    k_scan_add <<<dim3(NBLK, 2), 1024>>>();                                // 5
    k_fill     <<<(N_PAIRS + 255) / 256, 256>>>(H);                        // 6

    // ----- layer 0 (rest) -----
    k_edge_gather<HID0><<<N_EDGES, HID0 / 4>>>(p_h, p_fte);
    k_node_apply<HID0><<<N_NODES, HID0 / 4>>>(p_fte, b0, p_hout, l0k0, l0k1);

    // ----- layer 1 -----
    k_gemm<<<dim3((N_NODES + 127) / 128, HID1 / 128), 256>>>(p_hout, W1, p_h,
                                                             N_NODES, HID1, HID0);
    k_edge_gather<HID1><<<N_EDGES, HID1 / 4>>>(p_h, p_fte);

    // ----- fused: node apply + leaky + dropout + dropmax + pool -----
    k_node_dropmax<<<(N_NODES + 7) / 8, 256>>>(p_fte, b1, out + 32, p_pool,
                                               l1k0, l1k1);
    k_final<<<1, 128>>>(Wfc, bfc, out);
}

// round 15
// speedup vs baseline: 1.6238x; 1.0489x over previous
#include <cuda_runtime.h>
#include <stdint.h>

#define N_NODES 50000
#define N_EDGES 50000
#define N_PAIRS 800000
#define IN_CH   512
#define HID0    256
#define HID1    128
#define N_TGT   32

// ---------------- scratch (static device globals; no cudaMalloc allowed) ----
__device__ __align__(16) float g_h   [(size_t)N_NODES * HID0];
__device__ __align__(16) float g_fte [(size_t)N_EDGES * HID0];
__device__ __align__(16) float g_hout[(size_t)N_NODES * HID0];
__device__ float g_invDe[N_EDGES], g_invDn[N_NODES];
__device__ int   g_cnt_e[N_EDGES], g_cnt_n[N_NODES];
__device__ int   g_off_e[N_EDGES], g_off_n[N_NODES];
__device__ int   g_cur_e[N_EDGES], g_cur_n[N_NODES];
__device__ int   g_adj_e[N_PAIRS];
__device__ int   g_adj_n[N_PAIRS];
__device__ int   g_bsum[2][64];
__device__ float g_pool[HID1];

// ---------------- threefry2x32 (exact JAX semantics) ------------------------
__host__ __device__ __forceinline__ uint32_t rotl32(uint32_t x, int d) {
    return (x << d) | (x >> (32 - d));
}
__host__ __device__ __forceinline__ void threefry2x32(
    uint32_t k0, uint32_t k1, uint32_t x0, uint32_t x1,
    uint32_t& o0, uint32_t& o1)
{
    uint32_t k2 = k0 ^ k1 ^ 0x1BD11BDAu;
    x0 += k0; x1 += k1;
    x0 += x1; x1 = rotl32(x1,13); x1 ^= x0;
    x0 += x1; x1 = rotl32(x1,15); x1 ^= x0;
    x0 += x1; x1 = rotl32(x1,26); x1 ^= x0;
    x0 += x1; x1 = rotl32(x1, 6); x1 ^= x0;
    x0 += k1; x1 += k2 + 1u;
    x0 += x1; x1 = rotl32(x1,17); x1 ^= x0;
    x0 += x1; x1 = rotl32(x1,29); x1 ^= x0;
    x0 += x1; x1 = rotl32(x1,16); x1 ^= x0;
    x0 += x1; x1 = rotl32(x1,24); x1 ^= x0;
    x0 += k2; x1 += k0 + 2u;
    x0 += x1; x1 = rotl32(x1,13); x1 ^= x0;
    x0 += x1; x1 = rotl32(x1,15); x1 ^= x0;
    x0 += x1; x1 = rotl32(x1,26); x1 ^= x0;
    x0 += x1; x1 = rotl32(x1, 6); x1 ^= x0;
    x0 += k0; x1 += k1 + 3u;
    x0 += x1; x1 = rotl32(x1,17); x1 ^= x0;
    x0 += x1; x1 = rotl32(x1,29); x1 ^= x0;
    x0 += x1; x1 = rotl32(x1,16); x1 ^= x0;
    x0 += x1; x1 = rotl32(x1,24); x1 ^= x0;
    x0 += k1; x1 += k2 + 4u;
    x0 += x1; x1 = rotl32(x1,13); x1 ^= x0;
    x0 += x1; x1 = rotl32(x1,15); x1 ^= x0;
    x0 += x1; x1 = rotl32(x1,26); x1 ^= x0;
    x0 += x1; x1 = rotl32(x1, 6); x1 ^= x0;
    x0 += k2; x1 += k0 + 5u;
    o0 = x0; o1 = x1;
}

// ---------------- small setup kernels ---------------------------------------
__global__ void k_zero() {
    int i = blockIdx.x * blockDim.x + threadIdx.x;
    if (i < N_EDGES) g_cnt_e[i] = 0;
    if (i < N_NODES) g_cnt_n[i] = 0;
    if (i < HID1)    g_pool[i]  = 0.f;
}

__global__ void k_degree(const int* __restrict__ H) {
    int p = blockIdx.x * blockDim.x + threadIdx.x;
    if (p < N_PAIRS) {
        atomicAdd(&g_cnt_n[H[p]], 1);
        atomicAdd(&g_cnt_e[H[N_PAIRS + p]], 1);
    }
}

// ---------------- 3-phase parallel exclusive scan ----------------------------
__global__ void k_scan_part() {
    int arr = blockIdx.y;
    const int* cnt = arr ? g_cnt_n : g_cnt_e;
    int* off       = arr ? g_off_n : g_off_e;
    __shared__ int wsum[32];
    int i = blockIdx.x * 1024 + threadIdx.x;
    int lane = threadIdx.x & 31, w = threadIdx.x >> 5;
    int v = (i < N_EDGES) ? cnt[i] : 0;
    int x = v;
    #pragma unroll
    for (int o = 1; o < 32; o <<= 1) {
        int y = __shfl_up_sync(0xffffffffu, x, o);
        if (lane >= o) x += y;
    }
    if (lane == 31) wsum[w] = x;
    __syncthreads();
    if (w == 0) {
        int s = wsum[lane];
        #pragma unroll
        for (int o = 1; o < 32; o <<= 1) {
            int y = __shfl_up_sync(0xffffffffu, s, o);
            if (lane >= o) s += y;
        }
        wsum[lane] = s;
    }
    __syncthreads();
    int incl = x + ((w > 0) ? wsum[w - 1] : 0);
    if (i < N_EDGES) off[i] = incl - v;
    if (threadIdx.x == 1023) g_bsum[arr][blockIdx.x] = incl;
}

__global__ void k_scan_top() {
    int arr = blockIdx.x;
    __shared__ int s[64];
    int t = threadIdx.x;
    s[t] = (t < 49) ? g_bsum[arr][t] : 0;
    __syncthreads();
    #pragma unroll
    for (int o = 1; o < 64; o <<= 1) {
        int val = (t >= o) ? s[t - o] : 0;
        __syncthreads();
        s[t] += val;
        __syncthreads();
    }
    if (t < 49) g_bsum[arr][t] = s[t];
}

__global__ void k_scan_add() {
    int arr = blockIdx.y;
    int i = blockIdx.x * 1024 + threadIdx.x;
    if (i >= N_EDGES) return;
    int add = blockIdx.x ? g_bsum[arr][blockIdx.x - 1] : 0;
    if (arr == 0) {
        int o = g_off_e[i] + add;
        g_off_e[i] = o; g_cur_e[i] = o;
        g_invDe[i] = 1.0f / fmaxf((float)g_cnt_e[i], 1.0f);
    } else {
        int o = g_off_n[i] + add;
        g_off_n[i] = o; g_cur_n[i] = o;
        g_invDn[i] = 1.0f / fmaxf((float)g_cnt_n[i], 1.0f);
    }
}

__global__ void k_fill(const int* __restrict__ H) {
    int p = blockIdx.x * blockDim.x + threadIdx.x;
    if (p < N_PAIRS) {
        int n = H[p], e = H[N_PAIRS + p];
        g_adj_e[atomicAdd(&g_cur_e[e], 1)] = n;
        g_adj_n[atomicAdd(&g_cur_n[n], 1)] = e;
    }
}

// ---------------- SGEMM: 16x4 micro-tile, transposed-A broadcast ------------
#define FMA2(d, a, b) asm("fma.rn.f32x2 %0, %1, %2, %0;" : "+l"(d) : "l"(a), "l"(b))
#define BKT 16

__device__ __forceinline__ void cp16(uint32_t dst, const float* src) {
    asm volatile("cp.async.cg.shared.global [%0], [%1], 16;" :: "r"(dst), "l"(src));
}

__global__ void __launch_bounds__(256, 2)
k_gemm(const float* __restrict__ A, const float* __restrict__ B,
       float* __restrict__ C, int M, int N, int K) {
    __shared__ float At[2][BKT][136];    // transposed A: [kk][row]
    __shared__ float Bs[2][BKT][132];
    int tid = threadIdx.x;
    int bm = blockIdx.x * 128;
    int bn = blockIdx.y * 128;
    int warp = tid >> 5, lane = tid & 31;

    int arow = tid >> 1, acol = (tid & 1) << 3;
    int grow = bm + arow; if (grow > M - 1) grow = M - 1;
    const float* Abase = A + (size_t)grow * K + acol;
    int brow = tid >> 4, bcol = (tid & 15) << 3;
    const float* Bbase = B + (size_t)brow * N + bn + bcol;
    uint32_t asB[2];
    asB[0] = (uint32_t)__cvta_generic_to_shared(&Bs[0][brow][bcol]);
    asB[1] = (uint32_t)__cvta_generic_to_shared(&Bs[1][brow][bcol]);

    unsigned long long acc[16][2];
    #pragma unroll
    for (int r = 0; r < 16; r++) { acc[r][0] = 0ull; acc[r][1] = 0ull; }

    int T = K / BKT;

    float4 av0 = *(const float4*)(Abase);
    float4 av1 = *(const float4*)(Abase + 4);
    cp16(asB[0],      Bbase);
    cp16(asB[0] + 16, Bbase + 4);
    asm volatile("cp.async.commit_group;");
    At[0][acol + 0][arow] = av0.x; At[0][acol + 1][arow] = av0.y;
    At[0][acol + 2][arow] = av0.z; At[0][acol + 3][arow] = av0.w;
    At[0][acol + 4][arow] = av1.x; At[0][acol + 5][arow] = av1.y;
    At[0][acol + 6][arow] = av1.z; At[0][acol + 7][arow] = av1.w;
    asm volatile("cp.async.wait_group 0;");
    __syncthreads();

    for (int t = 0; t < T; t++) {
        int cur = t & 1, nxt = cur ^ 1;
        if (t + 1 < T) {
            av0 = *(const float4*)(Abase + (t + 1) * BKT);
            av1 = *(const float4*)(Abase + (t + 1) * BKT + 4);
            const float* bp = Bbase + (size_t)(t + 1) * BKT * N;
            cp16(asB[nxt],      bp);
            cp16(asB[nxt] + 16, bp + 4);
            asm volatile("cp.async.commit_group;");
        }

        const float* atw = &At[cur][0][warp * 16];
        #pragma unroll
        for (int kk = 0; kk < BKT; kk++) {
            float a[16];
            *(float4*)&a[0]  = *(const float4*)(atw + kk * 136);
            *(float4*)&a[4]  = *(const float4*)(atw + kk * 136 + 4);
            *(float4*)&a[8]  = *(const float4*)(atw + kk * 136 + 8);
            *(float4*)&a[12] = *(const float4*)(atw + kk * 136 + 12);
            ulonglong2 bb = *(const ulonglong2*)&Bs[cur][kk][lane * 4];
            #pragma unroll
            for (int r = 0; r < 16; r++) {
                unsigned long long a2;
                asm("mov.b64 %0, {%1, %1};" : "=l"(a2) : "f"(a[r]));
                FMA2(acc[r][0], a2, bb.x);
                FMA2(acc[r][1], a2, bb.y);
            }
        }

        if (t + 1 < T) {
            At[nxt][acol + 0][arow] = av0.x; At[nxt][acol + 1][arow] = av0.y;
            At[nxt][acol + 2][arow] = av0.z; At[nxt][acol + 3][arow] = av0.w;
            At[nxt][acol + 4][arow] = av1.x; At[nxt][acol + 5][arow] = av1.y;
            At[nxt][acol + 6][arow] = av1.z; At[nxt][acol + 7][arow] = av1.w;
            asm volatile("cp.async.wait_group 0;");
        }
        __syncthreads();
    }

    #pragma unroll
    for (int r = 0; r < 16; r++) {
        int row = bm + warp * 16 + r;
        if (row < M) {
            float2 p0 = *(float2*)&acc[r][0];
            float2 p1 = *(float2*)&acc[r][1];
            *(float4*)(C + (size_t)row * N + bn + lane * 4) =
                make_float4(p0.x, p0.y, p1.x, p1.y);
        }
    }
}

// ---------------- sparse gathers (CSR, float4-vectorized) --------------------
template<int C>
__global__ void k_edge_gather(const float* __restrict__ h, float* __restrict__ fte) {
    int e = blockIdx.x;
    int c4 = threadIdx.x;
    int s = g_off_e[e], m = g_cnt_e[e];
    const int* adj = g_adj_e + s;
    const float4* h4 = (const float4*)h;
    float4 acc = make_float4(0.f, 0.f, 0.f, 0.f);
    int j = 0;
    for (; j + 4 <= m; j += 4) {
        int n0 = adj[j], n1 = adj[j + 1], n2 = adj[j + 2], n3 = adj[j + 3];
        float4 a = h4[(size_t)n0 * (C / 4) + c4];
        float4 b = h4[(size_t)n1 * (C / 4) + c4];
        float4 d = h4[(size_t)n2 * (C / 4) + c4];
        float4 f = h4[(size_t)n3 * (C / 4) + c4];
        acc.x += a.x + b.x + d.x + f.x;
        acc.y += a.y + b.y + d.y + f.y;
        acc.z += a.z + b.z + d.z + f.z;
        acc.w += a.w + b.w + d.w + f.w;
    }
    for (; j < m; j++) {
        float4 a = h4[(size_t)adj[j] * (C / 4) + c4];
        acc.x += a.x; acc.y += a.y; acc.z += a.z; acc.w += a.w;
    }
    float inv = g_invDe[e];
    acc.x *= inv; acc.y *= inv; acc.z *= inv; acc.w *= inv;
    ((float4*)fte)[(size_t)e * (C / 4) + c4] = acc;
}

// node aggregation + bias + leaky relu + fused threefry dropout (layer 0)
template<int C>
__global__ void k_node_apply(const float* __restrict__ fte,
                             const float* __restrict__ bias,
                             float* __restrict__ out,
                             uint32_t dk0, uint32_t dk1) {
    int n = blockIdx.x;
    int c4 = threadIdx.x;
    int s = g_off_n[n], m = g_cnt_n[n];
    const int* adj = g_adj_n + s;
    const float4* f4 = (const float4*)fte;
    float4 acc = make_float4(0.f, 0.f, 0.f, 0.f);
    int j = 0;
    for (; j + 4 <= m; j += 4) {
        int e0 = adj[j], e1 = adj[j + 1], e2 = adj[j + 2], e3 = adj[j + 3];
        float4 a = f4[(size_t)e0 * (C / 4) + c4];
        float4 b = f4[(size_t)e1 * (C / 4) + c4];
        float4 d = f4[(size_t)e2 * (C / 4) + c4];
        float4 f = f4[(size_t)e3 * (C / 4) + c4];
        acc.x += a.x + b.x + d.x + f.x;
        acc.y += a.y + b.y + d.y + f.y;
        acc.z += a.z + b.z + d.z + f.z;
        acc.w += a.w + b.w + d.w + f.w;
    }
    for (; j < m; j++) {
        float4 a = f4[(size_t)adj[j] * (C / 4) + c4];
        acc.x += a.x; acc.y += a.y; acc.z += a.z; acc.w += a.w;
    }
    float inv = g_invDn[n];
    float4 bv = ((const float4*)bias)[c4];
    float v[4] = {acc.x * inv + bv.x, acc.y * inv + bv.y,
                  acc.z * inv + bv.z, acc.w * inv + bv.w};
    uint32_t base = (uint32_t)n * C + c4 * 4;
    #pragma unroll
    for (int q = 0; q < 4; q++) {
        float t = v[q];
        t = (t >= 0.f) ? t : 0.01f * t;
        uint32_t o0, o1;
        threefry2x32(dk0, dk1, 0u, base + q, o0, o1);
        v[q] = (((o0 ^ o1) >> 31) == 0u) ? t * 2.0f : 0.0f;
    }
    ((float4*)out)[(size_t)n * (C / 4) + c4] = make_float4(v[0], v[1], v[2], v[3]);
}

// ---- layer-1 node apply FUSED with dropmax + pool (one node per warp) -------
__global__ void k_node_dropmax(const float* __restrict__ fte,
                               const float* __restrict__ bias,
                               float* __restrict__ feats,
                               float* __restrict__ pool,
                               uint32_t dk0, uint32_t dk1) {
    __shared__ float s_pool[HID1];
    int t = threadIdx.x;
    if (t < HID1) s_pool[t] = 0.f;
    __syncthreads();
    int warp = t >> 5, lane = t & 31;
    int n = blockIdx.x * 8 + warp;
    if (n < N_NODES) {
        int s = g_off_n[n], m = g_cnt_n[n];
        const int* adj = g_adj_n + s;
        const float4* f4 = (const float4*)fte;
        float4 acc = make_float4(0.f, 0.f, 0.f, 0.f);
        int j = 0;
        for (; j + 4 <= m; j += 4) {
            int e0 = adj[j], e1 = adj[j + 1], e2 = adj[j + 2], e3 = adj[j + 3];
            float4 a = f4[(size_t)e0 * (HID1 / 4) + lane];
            float4 b = f4[(size_t)e1 * (HID1 / 4) + lane];
            float4 d = f4[(size_t)e2 * (HID1 / 4) + lane];
            float4 f = f4[(size_t)e3 * (HID1 / 4) + lane];
            acc.x += a.x + b.x + d.x + f.x;
            acc.y += a.y + b.y + d.y + f.y;
            acc.z += a.z + b.z + d.z + f.z;
            acc.w += a.w + b.w + d.w + f.w;
        }
        for (; j < m; j++) {
            float4 a = f4[(size_t)adj[j] * (HID1 / 4) + lane];
            acc.x += a.x; acc.y += a.y; acc.z += a.z; acc.w += a.w;
        }
        float inv = g_invDn[n];
        float4 bv = ((const float4*)bias)[lane];
        float v[4] = {acc.x * inv + bv.x, acc.y * inv + bv.y,
                      acc.z * inv + bv.z, acc.w * inv + bv.w};
        uint32_t base = (uint32_t)n * HID1 + lane * 4;
        #pragma unroll
        for (int q = 0; q < 4; q++) {
            float x = v[q];
            x = (x >= 0.f) ? x : 0.01f * x;
            uint32_t o0, o1;
            threefry2x32(dk0, dk1, 0u, base + q, o0, o1);
            v[q] = (((o0 ^ o1) >> 31) == 0u) ? x * 2.0f : 0.0f;
        }
        unsigned long long key[4];
        bool rem[4] = {false, false, false, false};
        #pragma unroll
        for (int q = 0; q < 4; q++) {
            uint32_t b = __float_as_uint(v[q]);
            uint32_t ord = (b & 0x80000000u) ? ~b : (b | 0x80000000u);
            key[q] = ((unsigned long long)ord << 32) |
                     (unsigned long long)(uint32_t)(127 - (lane * 4 + q));
        }
        for (int it = 0; it < 12; it++) {
            unsigned long long best = 0ull;
            #pragma unroll
            for (int q = 0; q < 4; q++) if (!rem[q] && key[q] > best) best = key[q];
            #pragma unroll
            for (int o = 16; o > 0; o >>= 1) {
                unsigned long long other = __shfl_xor_sync(0xffffffffu, best, o);
                if (other > best) best = other;
            }
            #pragma unroll
            for (int q = 0; q < 4; q++) if (key[q] == best) rem[q] = true;
        }
        #pragma unroll
        for (int q = 0; q < 4; q++) if (rem[q]) v[q] = 0.f;
        ((float4*)feats)[(size_t)n * (HID1 / 4) + lane] =
            make_float4(v[0], v[1], v[2], v[3]);
        #pragma unroll
        for (int q = 0; q < 4; q++) atomicAdd(&s_pool[lane * 4 + q], v[q]);
    }
    __syncthreads();
    if (t < HID1) atomicAdd(&pool[t], s_pool[t]);
}

// ---------------- head: mean, fc, sigmoid ------------------------------------
__global__ void k_final(const float* __restrict__ Wfc, const float* __restrict__ bfc,
                        float* __restrict__ d_out) {
    __shared__ float p[HID1];
    int t = threadIdx.x;
    if (t < HID1) {
        float pv = g_pool[t] * (1.0f / (float)N_NODES);
        p[t] = pv;
        d_out[32 + (size_t)N_NODES * HID1 + t] = pv;
    }
    __syncthreads();
    if (t < N_TGT) {
        float acc = bfc[t];
        #pragma unroll 8
        for (int c = 0; c < HID1; c++) acc += p[c] * Wfc[c * N_TGT + t];
        d_out[t] = 1.0f / (1.0f + expf(-acc));
    }
}

// ---------------- launch ------------------------------------------------------
extern "C" void kernel_launch(void* const* d_in, const int* in_sizes, int n_in,
                              void* d_out, int out_size) {
    const float* x   = (const float*)d_in[0];
    const int*   H   = (const int*)  d_in[1];
    const float* W0  = (const float*)d_in[2];
    const float* b0  = (const float*)d_in[3];
    const float* W1  = (const float*)d_in[4];
    const float* b1  = (const float*)d_in[5];
    const float* Wfc = (const float*)d_in[6];
    const float* bfc = (const float*)d_in[7];
    float* out = (float*)d_out;

    float *p_h, *p_fte, *p_hout, *p_pool;
    cudaGetSymbolAddress((void**)&p_h,    g_h);
    cudaGetSymbolAddress((void**)&p_fte,  g_fte);
    cudaGetSymbolAddress((void**)&p_hout, g_hout);
    cudaGetSymbolAddress((void**)&p_pool, g_pool);

    // side stream + fork/join events (created once on first, uncaptured call;
    // reused inside graph capture -> identical DAG every call)
    static cudaStream_t s_b = 0;
    static cudaEvent_t  e_fork = 0, e_join = 0;
    if (!s_b) {
        cudaStreamCreateWithFlags(&s_b, cudaStreamNonBlocking);
        cudaEventCreateWithFlags(&e_fork, cudaEventDisableTiming);
        cudaEventCreateWithFlags(&e_join, cudaEventDisableTiming);
    }

    uint32_t l0k0, l0k1, l1k0, l1k1;
    threefry2x32(0u, 42u, 0u, 0u, l0k0, l0k1);
    threefry2x32(0u, 42u, 0u, 1u, l1k0, l1k1);

    const int NBLK = (N_EDGES + 1023) / 1024;   // 49

    // ---- fork: CSR setup chain on s_b, GEMM0 on main (independent) ---------
    cudaEventRecord(e_fork, 0);
    cudaStreamWaitEvent(s_b, e_fork, 0);

    k_zero     <<<196, 256, 0, s_b>>>();
    k_degree   <<<(N_PAIRS + 255) / 256, 256, 0, s_b>>>(H);
    k_scan_part<<<dim3(NBLK, 2), 1024, 0, s_b>>>();
    k_scan_top <<<2, 64, 0, s_b>>>();
    k_scan_add <<<dim3(NBLK, 2), 1024, 0, s_b>>>();
    k_fill     <<<(N_PAIRS + 255) / 256, 256, 0, s_b>>>(H);

    k_gemm<<<dim3((N_NODES + 127) / 128, HID0 / 128), 256>>>(x, W0, p_h,
                                                             N_NODES, HID0, IN_CH);

    cudaEventRecord(e_join, s_b);
    cudaStreamWaitEvent(0, e_join, 0);

    // ----- layer 0 (rest) -----
    k_edge_gather<HID0><<<N_EDGES, HID0 / 4>>>(p_h, p_fte);
    k_node_apply<HID0><<<N_NODES, HID0 / 4>>>(p_fte, b0, p_hout, l0k0, l0k1);

    // ----- layer 1 -----
    k_gemm<<<dim3((N_NODES + 127) / 128, HID1 / 128), 256>>>(p_hout, W1, p_h,
                                                             N_NODES, HID1, HID0);
    k_edge_gather<HID1><<<N_EDGES, HID1 / 4>>>(p_h, p_fte);

    // ----- fused: node apply + leaky + dropout + dropmax + pool -----
    k_node_dropmax<<<(N_NODES + 7) / 8, 256>>>(p_fte, b1, out + 32, p_pool,
                                               l1k0, l1k1);
    k_final<<<1, 128>>>(Wfc, bfc, out);
}